// round 12
// baseline (speedup 1.0000x reference)
#include <cuda_runtime.h>
#include <cuda_bf16.h>
#include <cstdint>

typedef unsigned long long ull;

// ---- packed f32x2 helpers -------------------------------------------------
__device__ __forceinline__ ull pk2(float lo, float hi) {
    ull r; asm("mov.b64 %0, {%1, %2};" : "=l"(r) : "f"(lo), "f"(hi)); return r;
}
__device__ __forceinline__ ull bc2(float v) { return pk2(v, v); }
__device__ __forceinline__ void ffma2(ull& d, ull a, ull b) {
    asm("fma.rn.f32x2 %0, %1, %2, %3;" : "=l"(d) : "l"(a), "l"(b), "l"(d));
}
__device__ __forceinline__ float2 up2(ull v) {
    float2 f; asm("mov.b64 {%0, %1}, %2;" : "=f"(f.x), "=f"(f.y) : "l"(v)); return f;
}

// ---------------- scratch buffers ------------------------------------------
__device__ float g_buf1[64u*32u*132u*132u]; // conv1 out
__device__ float g_buf2[64u*32u*66u*66u];   // region+pool+bn2 out
__device__ float g_buf3[64u*16u*59u*59u];   // conv2 out
__device__ float g_buf4[64u*16u*52u*52u];   // conv3 out
__device__ float g_buf5[64u*16u*24u*24u];   // conv4 out
__device__ float g_buf6[64u*16u*20u*20u];   // conv5 out (fc input)
__device__ float g_fc1o[64u*4096u];
__device__ float g_fc2o[64u*2048u];
__device__ float g_dummy[32];

// dummy launches: land the ncu fixed-index capture window (4th launch) on region
__global__ void nudge_kernel(float* p) { p[threadIdx.x] = 0.f; }

// ===========================================================================
// conv1: (64,3,142,142) -> (64,32,132,132), 11x11 VALID  (round-4 f32x2)
// At ~99% of the measured FFMA2-pipe limit — do not touch.
// ===========================================================================
__global__ void __launch_bounds__(264, 2)
conv1_kernel(const float* __restrict__ x,
             const float* __restrict__ w,
             const float* __restrict__ bias,
             float* __restrict__ out) {
    __shared__ float  s_in[3*32*76];
    __shared__ float2 s_w2[2*363];
    const int t   = blockIdx.x;
    const int ti  = t >> 1, tj = t & 1;
    const int gy0 = ti * 22, gx0 = tj * 66;
    const int ocg = blockIdx.y;
    const int b   = blockIdx.z;
    const int tid = threadIdx.x;

    for (int i = tid; i < 2*363; i += 264) {
        int h = i / 363, idx = i % 363;
        int oc = ocg*4 + h*2;
        s_w2[i] = make_float2(w[oc*363 + idx], w[(oc+1)*363 + idx]);
    }
    for (int i = tid; i < 3*32*76; i += 264) {
        int c  = i / 2432;
        int r  = (i / 76) % 32, cc = i % 76;
        s_in[i] = x[((b*3 + c)*142 + gy0 + r)*142 + gx0 + cc];
    }
    __syncthreads();

    const int half = tid / 132;
    const int s    = tid % 132;
    const int row  = s / 6;
    const int cs   = (s % 6) * 11;

    ull acc2[11];
#pragma unroll
    for (int j = 0; j < 11; j++) acc2[j] = 0ull;

    for (int c = 0; c < 3; c++) {
        for (int ky = 0; ky < 11; ky++) {
            const float* ip = &s_in[c*2432 + (row + ky)*76 + cs];
            ull ivb[21];
#pragma unroll
            for (int j = 0; j < 21; j++) ivb[j] = bc2(ip[j]);
            const float2* wrow = &s_w2[half*363 + c*121 + ky*11];
#pragma unroll
            for (int kx = 0; kx < 11; kx++) {
                ull w2 = *(const ull*)&wrow[kx];
#pragma unroll
                for (int j = 0; j < 11; j++)
                    ffma2(acc2[j], ivb[kx + j], w2);
            }
        }
    }
    const int oc = ocg*4 + half*2;
    const float b0 = bias[oc], b1 = bias[oc+1];
    float* o0 = &out[(((long)b*32 + oc)*132 + gy0 + row)*132 + gx0 + cs];
    float* o1 = o0 + 132*132;
#pragma unroll
    for (int j = 0; j < 11; j++) {
        float2 f = up2(acc2[j]);
        o0[j] = f.x + b0;
        o1[j] = f.y + b1;
    }
}

// ===========================================================================
// region layer fused.  CHANGE: input staged as PRE-PACKED f32x2 pairs
// (pair[x] = (v[x], v[x+1])) -> compute loop has 7 broadcast LDS.64 per
// row and ZERO pk2 packs.  Weights stay [(icl*9+k)*33+oc] (conflict-free).
// Dynamic smem: pairs 16*20*20 ull (51200B) + weights 4752 f (19008B).
// ===========================================================================
__global__ void __launch_bounds__(288)
region_kernel(const float* __restrict__ xin,
              const float* __restrict__ rg_g, const float* __restrict__ rg_b,
              const float* __restrict__ rg_m, const float* __restrict__ rg_v,
              const float* __restrict__ rg_w, const float* __restrict__ rg_cb,
              const float* __restrict__ bn2_g, const float* __restrict__ bn2_b,
              const float* __restrict__ bn2_m, const float* __restrict__ bn2_v,
              float* __restrict__ out) {
    extern __shared__ __align__(8) ull dyn[];
    ull*   s_pair  = dyn;                    // 16 * hp * wp pairs (<= 6400)
    float* s_w     = (float*)(dyn + 6400);   // 144*33 = 4752 floats
    float* s_stage = (float*)dyn;            // reuse for conv-out staging
    __shared__ float s_scale[32], s_shift[32], s_cb[32], s_a2[32], s_b2[32];

    const int tile = blockIdx.x;
    const int b    = blockIdx.y;
    const int ti = tile >> 3, tj = tile & 7;
    const int th = (ti < 7) ? 18 : 6, tw = (tj < 7) ? 18 : 6;
    const int gy0 = ti * 18, gx0 = tj * 18;
    const int tid = threadIdx.x;

    if (tid < 32) {
        int p = tile*32 + tid;
        float a = rg_g[p] * rsqrtf(rg_v[p] + 1e-5f);
        s_scale[tid] = a;
        s_shift[tid] = rg_b[p] - rg_m[p]*a;
        s_cb[tid]    = rg_cb[p];
    } else if (tid < 64) {
        int c = tid - 32;
        float a2 = bn2_g[c] * rsqrtf(bn2_v[c] + 1e-5f);
        s_a2[c] = a2;
        s_b2[c] = bn2_b[c] - bn2_m[c]*a2;
    }

    const int hp = th + 2, wp = tw + 2;
    const int npx = tw / 6, npy = th / 6;
    const int pos = tid >> 5;
    const int oc  = tid & 31;
    const bool active = pos < npx * npy;
    const int prow = (pos / npx) * 6;
    const int pcol = (pos % npx) * 6;

    ull acc2[6][3];
#pragma unroll
    for (int i = 0; i < 6; i++)
#pragma unroll
        for (int j = 0; j < 3; j++) acc2[i][j] = 0ull;

    for (int chunk = 0; chunk < 2; chunk++) {
        const int ic0 = chunk * 16;
        __syncthreads();
        // stage BN+ReLU input as packed pairs: pair[x] = (v[x], v[x+1])
        const int nin = 16 * hp * wp;
        for (int i = tid; i < nin; i += 288) {
            int icl = i / (hp*wp);
            int r = i % (hp*wp);
            int y = r / wp, xx = r % wp;
            float v0 = 0.f, v1 = 0.f;
            if (y > 0 && y < hp-1) {
                const float* rowp = &xin[(((long)b*32 + ic0 + icl)*132 + gy0 + y - 1)*132 + gx0 - 1];
                float sc = s_scale[ic0+icl], sh = s_shift[ic0+icl];
                if (xx > 0 && xx < wp-1)  v0 = fmaxf(sc*rowp[xx]   + sh, 0.f);
                if (xx + 1 < wp-1)        v1 = fmaxf(sc*rowp[xx+1] + sh, 0.f);
            }
            s_pair[i] = pk2(v0, v1);
        }
        // weights: gmem read coalesced over kk; smem write stride-33 (conflict-free)
        for (int i = tid; i < 32*144; i += 288) {
            int o  = i / 144;          // oc
            int kk = i % 144;          // icl*9 + k
            s_w[kk*33 + o] = rg_w[(long)tile*9216 + o*288 + ic0*9 + kk];
        }
        __syncthreads();

        if (active) {
            for (int icl = 0; icl < 16; icl++) {
                ull wr2[9];
#pragma unroll
                for (int k = 0; k < 9; k++) wr2[k] = bc2(s_w[(icl*9 + k)*33 + oc]);
                const ull* pb = &s_pair[icl*hp*wp + prow*wp + pcol];
#pragma unroll
                for (int r = 0; r < 8; r++) {
                    ull p[7];
#pragma unroll
                    for (int i = 0; i < 7; i++) p[i] = pb[r*wp + i];
#pragma unroll
                    for (int ky = 0; ky < 3; ky++) {
                        int orow = r - ky;
                        if (orow >= 0 && orow < 6) {
#pragma unroll
                            for (int kx = 0; kx < 3; kx++) {
                                ull w2 = wr2[ky*3 + kx];
                                ffma2(acc2[orow][0], p[kx    ], w2);
                                ffma2(acc2[orow][1], p[kx + 2], w2);
                                ffma2(acc2[orow][2], p[kx + 4], w2);
                            }
                        }
                    }
                }
            }
        }
    }

    __syncthreads();
    if (active) {
        const float cb = s_cb[oc];
#pragma unroll
        for (int i = 0; i < 6; i++)
#pragma unroll
            for (int jp = 0; jp < 3; jp++) {
                float2 f = up2(acc2[i][jp]);
                s_stage[(oc*th + prow + i)*tw + pcol + 2*jp    ] = f.x + cb;
                s_stage[(oc*th + prow + i)*tw + pcol + 2*jp + 1] = f.y + cb;
            }
    }
    __syncthreads();

    const int ph = th / 2, pw = tw / 2;
    const int npool = 32 * ph * pw;
    for (int i = tid; i < npool; i += 288) {
        int c = i / (ph*pw);
        int r = i % (ph*pw);
        int py = r / pw, px = r % pw;
        const float* cp = &s_stage[(c*th + 2*py)*tw + 2*px];
        const float* rp = &xin[(((long)b*32 + c)*132 + gy0 + 2*py)*132 + gx0 + 2*px];
        float v00 = fmaxf(cp[0]    + rp[0],     0.f);
        float v01 = fmaxf(cp[1]    + rp[1],     0.f);
        float v10 = fmaxf(cp[tw]   + rp[132],   0.f);
        float v11 = fmaxf(cp[tw+1] + rp[133],   0.f);
        float m = fmaxf(fmaxf(v00, v01), fmaxf(v10, v11));
        out[(((long)b*32 + c)*66 + ti*9 + py)*66 + tj*9 + px] = s_a2[c]*m + s_b2[c];
    }
}

// ===========================================================================
// conv2 / conv3: f32x2, (256,2) — measured-best; unchanged
// ===========================================================================
template<int CIN, int HIN, int WIN, int HOUT, int WOUT>
__global__ void __launch_bounds__(256, 2)
conv8x8_relu_kernel(const float* __restrict__ in,
                    const float* __restrict__ w,
                    const float* __restrict__ bias,
                    float* __restrict__ out) {
    __shared__ float  s_in[8*15*40];
    __shared__ float2 s_w2[8*8*64];
    const int x0 = blockIdx.x * 32, y0 = blockIdx.y * 8;
    const int b = blockIdx.z;
    const int tid = threadIdx.x;
    const int pr  = tid >> 5;
    const int s   = tid & 31;
    const int row = s >> 2;
    const int cs  = (s & 3) * 8;

    ull acc2[8];
#pragma unroll
    for (int j = 0; j < 8; j++) acc2[j] = 0ull;

    for (int chunk = 0; chunk < CIN/8; chunk++) {
        const int ic0 = chunk * 8;
        __syncthreads();
        for (int i = tid; i < 8*15*40; i += 256) {
            int icl = i / 600;
            int r = (i / 40) % 15, c = i % 40;
            int iy = y0 + r, ix = x0 + c;
            float v = 0.f;
            if (c < 39 && iy < HIN && ix < WIN)
                v = in[(((long)b*CIN + ic0 + icl)*HIN + iy)*WIN + ix];
            s_in[i] = v;
        }
        for (int i = tid; i < 8*512; i += 256) {
            int p = i >> 9;
            int r = i & 511;
            float w0 = w[(2*p    )*CIN*64 + ic0*64 + r];
            float w1 = w[(2*p + 1)*CIN*64 + ic0*64 + r];
            s_w2[i] = make_float2(w0, w1);
        }
        __syncthreads();

        for (int icl = 0; icl < 8; icl++) {
#pragma unroll
            for (int ky = 0; ky < 8; ky++) {
                const float* ip = &s_in[icl*600 + (row + ky)*40 + cs];
                float4 v0 = *(const float4*)(ip);
                float4 v1 = *(const float4*)(ip + 4);
                float4 v2 = *(const float4*)(ip + 8);
                float4 v3 = *(const float4*)(ip + 12);
                ull ivb[15];
                ivb[0]=bc2(v0.x); ivb[1]=bc2(v0.y); ivb[2]=bc2(v0.z); ivb[3]=bc2(v0.w);
                ivb[4]=bc2(v1.x); ivb[5]=bc2(v1.y); ivb[6]=bc2(v1.z); ivb[7]=bc2(v1.w);
                ivb[8]=bc2(v2.x); ivb[9]=bc2(v2.y); ivb[10]=bc2(v2.z); ivb[11]=bc2(v2.w);
                ivb[12]=bc2(v3.x); ivb[13]=bc2(v3.y); ivb[14]=bc2(v3.z);
                const float2* wrow = &s_w2[(pr*8 + icl)*64 + ky*8];
#pragma unroll
                for (int kx = 0; kx < 8; kx++) {
                    ull w2 = *(const ull*)&wrow[kx];
#pragma unroll
                    for (int j = 0; j < 8; j++)
                        ffma2(acc2[j], ivb[kx + j], w2);
                }
            }
        }
    }

    const int oy = y0 + row;
    if (oy < HOUT) {
        const int oc0 = 2*pr;
        const float b0 = bias[oc0], b1 = bias[oc0 + 1];
        float* o0 = &out[(((long)b*16 + oc0)*HOUT + oy)*WOUT];
        float* o1 = o0 + (long)HOUT*WOUT;
#pragma unroll
        for (int j = 0; j < 8; j++) {
            int ox = x0 + cs + j;
            if (ox < WOUT) {
                float2 f = up2(acc2[j]);
                o0[ox] = fmaxf(f.x + b0, 0.f);
                o1[ox] = fmaxf(f.y + b1, 0.f);
            }
        }
    }
}

// ===========================================================================
// conv4 (unchanged)
// ===========================================================================
__global__ void conv4_kernel(const float* __restrict__ in,
                             const float* __restrict__ w,
                             const float* __restrict__ bias,
                             float* __restrict__ out) {
    __shared__ float s_in[8*16*52];
    __shared__ float s_w[16*8*36];
    const int band = blockIdx.x;
    const int b = blockIdx.y;
    const int tid = threadIdx.x;
    const int ry0 = band * 6;

    float acc[9];
#pragma unroll
    for (int t = 0; t < 9; t++) acc[t] = 0.f;

    for (int chunk = 0; chunk < 2; chunk++) {
        const int ic0 = chunk * 8;
        __syncthreads();
        for (int i = tid; i < 8*16*52; i += 256) {
            int icl = i / (16*52);
            int r = (i / 52) % 16, c = i % 52;
            s_in[i] = in[(((long)b*16 + ic0 + icl)*52 + 12*band + r)*52 + c];
        }
        for (int i = tid; i < 16*8*36; i += 256) {
            int o = i / (8*36);
            int r = i % (8*36);
            int icl = r / 36, k = r % 36;
            s_w[i] = w[(o*16 + ic0 + icl)*36 + k];
        }
        __syncthreads();
#pragma unroll
        for (int t = 0; t < 9; t++) {
            int task = tid + t*256;
            if (task < 2304) {
                int oc = task / 144;
                int r = task % 144;
                int row = r / 24, cx = r % 24;
                float a = acc[t];
                for (int icl = 0; icl < 8; icl++) {
#pragma unroll
                    for (int ky = 0; ky < 6; ky++) {
                        const float* rp = &s_in[(icl*16 + 2*row + ky)*52 + 2*cx];
                        const float* wpp = &s_w[(oc*8 + icl)*36 + ky*6];
#pragma unroll
                        for (int kx = 0; kx < 6; kx++) a += rp[kx] * wpp[kx];
                    }
                }
                acc[t] = a;
            }
        }
    }
#pragma unroll
    for (int t = 0; t < 9; t++) {
        int task = tid + t*256;
        if (task < 2304) {
            int oc = task / 144;
            int r = task % 144;
            int row = r / 24, cx = r % 24;
            out[(((long)b*16 + oc)*24 + ry0 + row)*24 + cx] = fmaxf(acc[t] + bias[oc], 0.f);
        }
    }
}

// ===========================================================================
// conv5 (unchanged)
// ===========================================================================
__global__ void conv5_kernel(const float* __restrict__ in,
                             const float* __restrict__ w,
                             const float* __restrict__ bias,
                             float* __restrict__ out) {
    __shared__ float s_in[16*14*24];
    __shared__ float s_w[16*16*25];
    const int band = blockIdx.x;
    const int b = blockIdx.y;
    const int tid = threadIdx.x;
    const int ry0 = band * 10;

    for (int i = tid; i < 16*14*24; i += 256) {
        int icl = i / (14*24);
        int r = (i / 24) % 14, c = i % 24;
        s_in[i] = in[(((long)b*16 + icl)*24 + ry0 + r)*24 + c];
    }
    for (int i = tid; i < 16*16*25; i += 256)
        s_w[i] = w[i];
    __syncthreads();

#pragma unroll
    for (int t = 0; t < 13; t++) {
        int task = tid + t*256;
        if (task < 3200) {
            int oc = task / 200;
            int r = task % 200;
            int row = r / 20, cx = r % 20;
            float a = 0.f;
            for (int ic = 0; ic < 16; ic++) {
#pragma unroll
                for (int ky = 0; ky < 5; ky++) {
                    const float* rp = &s_in[(ic*14 + row + ky)*24 + cx];
                    const float* wpp = &s_w[(oc*16 + ic)*25 + ky*5];
#pragma unroll
                    for (int kx = 0; kx < 5; kx++) a += rp[kx] * wpp[kx];
                }
            }
            out[(((long)b*16 + oc)*20 + ry0 + row)*20 + cx] = fmaxf(a + bias[oc], 0.f);
        }
    }
}

// ===========================================================================
// GEMM for fc1/fc2 (unchanged)
// ===========================================================================
__global__ void __launch_bounds__(256)
gemm_relu_kernel(const float* __restrict__ X,
                 const float* __restrict__ W,
                 const float* __restrict__ bias,
                 float* __restrict__ out,
                 int N, int K) {
    __shared__ float xs[64][68];
    __shared__ float ws[64][68];
    const int n0 = blockIdx.x * 64;
    const int tid = threadIdx.x;
    const int tx = tid & 15, ty = tid >> 4;

    float acc[4][4];
#pragma unroll
    for (int i = 0; i < 4; i++)
#pragma unroll
        for (int j = 0; j < 4; j++) acc[i][j] = 0.f;

    for (int k0 = 0; k0 < K; k0 += 64) {
        __syncthreads();
        for (int i = tid; i < 64*64; i += 256) {
            int m = i >> 6, k = i & 63;
            xs[k][m] = X[m*K + k0 + k];
        }
        for (int i = tid; i < 64*64; i += 256) {
            int n = i >> 6, k = i & 63;
            ws[k][n] = W[(long)(n0 + n)*K + k0 + k];
        }
        __syncthreads();
#pragma unroll 8
        for (int k = 0; k < 64; k++) {
            float4 a4 = *(const float4*)&xs[k][ty*4];
            float4 b4 = *(const float4*)&ws[k][tx*4];
            float a[4] = {a4.x, a4.y, a4.z, a4.w};
            float bb[4] = {b4.x, b4.y, b4.z, b4.w};
#pragma unroll
            for (int i = 0; i < 4; i++)
#pragma unroll
                for (int j = 0; j < 4; j++)
                    acc[i][j] += a[i] * bb[j];
        }
    }
#pragma unroll
    for (int i = 0; i < 4; i++) {
        int m = ty*4 + i;
#pragma unroll
        for (int j = 0; j < 4; j++) {
            int n = n0 + tx*4 + j;
            out[m*N + n] = fmaxf(acc[i][j] + bias[n], 0.f);
        }
    }
}

// ===========================================================================
// fc3 (unchanged)
// ===========================================================================
__global__ void fc3_kernel(const float* __restrict__ X,
                           const float* __restrict__ W,
                           const float* __restrict__ bias,
                           float* __restrict__ out) {
    const int warp = (blockIdx.x * 256 + threadIdx.x) >> 5;
    const int lane = threadIdx.x & 31;
    if (warp >= 768) return;
    const int m = warp / 12, n = warp % 12;
    float s = 0.f;
    for (int k = lane; k < 2048; k += 32)
        s += X[m*2048 + k] * W[n*2048 + k];
#pragma unroll
    for (int o = 16; o; o >>= 1) s += __shfl_xor_sync(0xFFFFFFFFu, s, o);
    if (lane == 0) out[m*12 + n] = s + bias[n];
}

// ===========================================================================
extern "C" void kernel_launch(void* const* d_in, const int* in_sizes, int n_in,
                              void* d_out, int out_size) {
    const float* x       = (const float*)d_in[0];
    const float* conv1_w = (const float*)d_in[1];
    const float* conv1_b = (const float*)d_in[2];
    const float* rg_g    = (const float*)d_in[3];
    const float* rg_b    = (const float*)d_in[4];
    const float* rg_m    = (const float*)d_in[5];
    const float* rg_v    = (const float*)d_in[6];
    const float* rg_w    = (const float*)d_in[7];
    const float* rg_cb   = (const float*)d_in[8];
    const float* bn2_g   = (const float*)d_in[9];
    const float* bn2_b   = (const float*)d_in[10];
    const float* bn2_m   = (const float*)d_in[11];
    const float* bn2_v   = (const float*)d_in[12];
    const float* conv2_w = (const float*)d_in[13];
    const float* conv2_b = (const float*)d_in[14];
    const float* conv3_w = (const float*)d_in[15];
    const float* conv3_b = (const float*)d_in[16];
    const float* conv4_w = (const float*)d_in[17];
    const float* conv4_b = (const float*)d_in[18];
    const float* conv5_w = (const float*)d_in[19];
    const float* conv5_b = (const float*)d_in[20];
    const float* fc1_w   = (const float*)d_in[21];
    const float* fc1_b   = (const float*)d_in[22];
    const float* fc2_w   = (const float*)d_in[23];
    const float* fc2_b   = (const float*)d_in[24];
    const float* fc3_w   = (const float*)d_in[25];
    const float* fc3_b   = (const float*)d_in[26];

    float *b1, *b2, *b3, *b4, *b5, *b6, *f1, *f2, *dm;
    cudaGetSymbolAddress((void**)&b1, g_buf1);
    cudaGetSymbolAddress((void**)&b2, g_buf2);
    cudaGetSymbolAddress((void**)&b3, g_buf3);
    cudaGetSymbolAddress((void**)&b4, g_buf4);
    cudaGetSymbolAddress((void**)&b5, g_buf5);
    cudaGetSymbolAddress((void**)&b6, g_buf6);
    cudaGetSymbolAddress((void**)&f1, g_fc1o);
    cudaGetSymbolAddress((void**)&f2, g_fc2o);
    cudaGetSymbolAddress((void**)&dm, g_dummy);

    // region dynamic smem: 6400 ull pairs + 4752 float weights = 70208 B
    const int RG_SMEM = 6400*8 + 4752*4;
    cudaFuncSetAttribute(region_kernel, cudaFuncAttributeMaxDynamicSharedMemorySize, RG_SMEM);

    // two tiny launches: ncu fixed-index capture (4th launch) lands on region
    nudge_kernel<<<1, 32>>>(dm);
    nudge_kernel<<<1, 32>>>(dm);

    conv1_kernel<<<dim3(12, 8, 64), 264>>>(x, conv1_w, conv1_b, b1);
    region_kernel<<<dim3(64, 64), 288, RG_SMEM>>>(b1, rg_g, rg_b, rg_m, rg_v, rg_w, rg_cb,
                                                  bn2_g, bn2_b, bn2_m, bn2_v, b2);
    conv8x8_relu_kernel<32, 66, 66, 59, 59><<<dim3(2, 8, 64), 256>>>(b2, conv2_w, conv2_b, b3);
    conv8x8_relu_kernel<16, 59, 59, 52, 52><<<dim3(2, 7, 64), 256>>>(b3, conv3_w, conv3_b, b4);
    conv4_kernel<<<dim3(4, 64), 256>>>(b4, conv4_w, conv4_b, b5);
    conv5_kernel<<<dim3(2, 64), 256>>>(b5, conv5_w, conv5_b, b6);
    gemm_relu_kernel<<<64, 256>>>(b6, fc1_w, fc1_b, f1, 4096, 6400);
    gemm_relu_kernel<<<32, 256>>>(f1, fc2_w, fc2_b, f2, 2048, 4096);
    fc3_kernel<<<96, 256>>>(f2, fc3_w, fc3_b, (float*)d_out);
}

// round 13
// speedup vs baseline: 1.0273x; 1.0273x over previous
#include <cuda_runtime.h>
#include <cuda_bf16.h>
#include <cstdint>

typedef unsigned long long ull;

// ---- packed f32x2 helpers -------------------------------------------------
__device__ __forceinline__ ull pk2(float lo, float hi) {
    ull r; asm("mov.b64 %0, {%1, %2};" : "=l"(r) : "f"(lo), "f"(hi)); return r;
}
__device__ __forceinline__ ull bc2(float v) { return pk2(v, v); }
__device__ __forceinline__ void ffma2(ull& d, ull a, ull b) {
    asm("fma.rn.f32x2 %0, %1, %2, %3;" : "=l"(d) : "l"(a), "l"(b), "l"(d));
}
__device__ __forceinline__ float2 up2(ull v) {
    float2 f; asm("mov.b64 {%0, %1}, %2;" : "=f"(f.x), "=f"(f.y) : "l"(v)); return f;
}

// ---------------- scratch buffers ------------------------------------------
__device__ float g_buf1[64u*32u*132u*132u]; // conv1 out
__device__ float g_buf2[64u*32u*66u*66u];   // region+pool+bn2 out
__device__ float g_buf3[64u*16u*59u*59u];   // conv2 out
__device__ float g_buf4[64u*16u*52u*52u];   // conv3 out
__device__ float g_buf5[64u*16u*24u*24u];   // conv4 out
__device__ float g_buf6[64u*16u*20u*20u];   // conv5 out (fc input)
__device__ float g_fc1o[64u*4096u];
__device__ float g_fc2o[64u*2048u];
__device__ float g_dummy[32];

// dummy launch: land the ncu fixed-index capture window (4th launch) on conv2
__global__ void nudge_kernel(float* p) { p[threadIdx.x] = 0.f; }

// ===========================================================================
// conv1: (64,3,142,142) -> (64,32,132,132), 11x11 VALID  (round-4 f32x2)
// At ~99% of the measured FFMA2-pipe limit — do not touch.
// ===========================================================================
__global__ void __launch_bounds__(264, 2)
conv1_kernel(const float* __restrict__ x,
             const float* __restrict__ w,
             const float* __restrict__ bias,
             float* __restrict__ out) {
    __shared__ float  s_in[3*32*76];
    __shared__ float2 s_w2[2*363];
    const int t   = blockIdx.x;
    const int ti  = t >> 1, tj = t & 1;
    const int gy0 = ti * 22, gx0 = tj * 66;
    const int ocg = blockIdx.y;
    const int b   = blockIdx.z;
    const int tid = threadIdx.x;

    for (int i = tid; i < 2*363; i += 264) {
        int h = i / 363, idx = i % 363;
        int oc = ocg*4 + h*2;
        s_w2[i] = make_float2(w[oc*363 + idx], w[(oc+1)*363 + idx]);
    }
    for (int i = tid; i < 3*32*76; i += 264) {
        int c  = i / 2432;
        int r  = (i / 76) % 32, cc = i % 76;
        s_in[i] = x[((b*3 + c)*142 + gy0 + r)*142 + gx0 + cc];
    }
    __syncthreads();

    const int half = tid / 132;
    const int s    = tid % 132;
    const int row  = s / 6;
    const int cs   = (s % 6) * 11;

    ull acc2[11];
#pragma unroll
    for (int j = 0; j < 11; j++) acc2[j] = 0ull;

    for (int c = 0; c < 3; c++) {
        for (int ky = 0; ky < 11; ky++) {
            const float* ip = &s_in[c*2432 + (row + ky)*76 + cs];
            ull ivb[21];
#pragma unroll
            for (int j = 0; j < 21; j++) ivb[j] = bc2(ip[j]);
            const float2* wrow = &s_w2[half*363 + c*121 + ky*11];
#pragma unroll
            for (int kx = 0; kx < 11; kx++) {
                ull w2 = *(const ull*)&wrow[kx];
#pragma unroll
                for (int j = 0; j < 11; j++)
                    ffma2(acc2[j], ivb[kx + j], w2);
            }
        }
    }
    const int oc = ocg*4 + half*2;
    const float b0 = bias[oc], b1 = bias[oc+1];
    float* o0 = &out[(((long)b*32 + oc)*132 + gy0 + row)*132 + gx0 + cs];
    float* o1 = o0 + 132*132;
#pragma unroll
    for (int j = 0; j < 11; j++) {
        float2 f = up2(acc2[j]);
        o0[j] = f.x + b0;
        o1[j] = f.y + b1;
    }
}

// ===========================================================================
// region layer fused — ROUND-11 version (measured best: 72 regs, 3 blk/SM).
// Conflict-free transposed weights; per-row pk2 packing kept (reg-cheap).
// ===========================================================================
__global__ void __launch_bounds__(288)
region_kernel(const float* __restrict__ xin,
              const float* __restrict__ rg_g, const float* __restrict__ rg_b,
              const float* __restrict__ rg_m, const float* __restrict__ rg_v,
              const float* __restrict__ rg_w, const float* __restrict__ rg_cb,
              const float* __restrict__ bn2_g, const float* __restrict__ bn2_b,
              const float* __restrict__ bn2_m, const float* __restrict__ bn2_v,
              float* __restrict__ out) {
    __shared__ float smem[11152];   // s_in(6400)+s_w(4752); staging reuses [0,10368)
    __shared__ float s_scale[32], s_shift[32], s_cb[32], s_a2[32], s_b2[32];

    const int tile = blockIdx.x;
    const int b    = blockIdx.y;
    const int ti = tile >> 3, tj = tile & 7;
    const int th = (ti < 7) ? 18 : 6, tw = (tj < 7) ? 18 : 6;
    const int gy0 = ti * 18, gx0 = tj * 18;
    const int tid = threadIdx.x;

    if (tid < 32) {
        int p = tile*32 + tid;
        float a = rg_g[p] * rsqrtf(rg_v[p] + 1e-5f);
        s_scale[tid] = a;
        s_shift[tid] = rg_b[p] - rg_m[p]*a;
        s_cb[tid]    = rg_cb[p];
    } else if (tid < 64) {
        int c = tid - 32;
        float a2 = bn2_g[c] * rsqrtf(bn2_v[c] + 1e-5f);
        s_a2[c] = a2;
        s_b2[c] = bn2_b[c] - bn2_m[c]*a2;
    }

    const int hp = th + 2, wp = tw + 2;
    const int npx = tw / 6, npy = th / 6;
    const int pos = tid >> 5;
    const int oc  = tid & 31;
    const bool active = pos < npx * npy;
    const int prow = (pos / npx) * 6;
    const int pcol = (pos % npx) * 6;

    float* s_in = smem;
    float* s_w  = smem + 6400;   // layout: [(icl*9+k)*33 + oc]

    ull acc2[6][3];
#pragma unroll
    for (int i = 0; i < 6; i++)
#pragma unroll
        for (int j = 0; j < 3; j++) acc2[i][j] = 0ull;

    for (int chunk = 0; chunk < 2; chunk++) {
        const int ic0 = chunk * 16;
        __syncthreads();
        const int nin = 16 * hp * wp;
        for (int i = tid; i < nin; i += 288) {
            int icl = i / (hp*wp);
            int r = i % (hp*wp);
            int y = r / wp, xx = r % wp;
            float v = 0.f;
            if (y > 0 && y < hp-1 && xx > 0 && xx < wp-1) {
                float raw = xin[(((long)b*32 + ic0 + icl)*132 + gy0 + y - 1)*132 + gx0 + xx - 1];
                v = fmaxf(s_scale[ic0+icl]*raw + s_shift[ic0+icl], 0.f);
            }
            s_in[i] = v;
        }
        for (int i = tid; i < 32*144; i += 288) {
            int o  = i / 144;          // oc
            int kk = i % 144;          // icl*9 + k
            s_w[kk*33 + o] = rg_w[(long)tile*9216 + o*288 + ic0*9 + kk];
        }
        __syncthreads();

        if (active) {
            for (int icl = 0; icl < 16; icl++) {
                ull wr2[9];
#pragma unroll
                for (int k = 0; k < 9; k++) wr2[k] = bc2(s_w[(icl*9 + k)*33 + oc]);
                const float* ib = &s_in[icl*hp*wp + prow*wp + pcol];
#pragma unroll
                for (int r = 0; r < 8; r++) {
                    float iv[8];
#pragma unroll
                    for (int j = 0; j < 8; j++) iv[j] = ib[r*wp + j];
                    ull p[7];
#pragma unroll
                    for (int i = 0; i < 7; i++) p[i] = pk2(iv[i], iv[i+1]);
#pragma unroll
                    for (int ky = 0; ky < 3; ky++) {
                        int orow = r - ky;
                        if (orow >= 0 && orow < 6) {
#pragma unroll
                            for (int kx = 0; kx < 3; kx++) {
                                ull w2 = wr2[ky*3 + kx];
                                ffma2(acc2[orow][0], p[kx    ], w2);
                                ffma2(acc2[orow][1], p[kx + 2], w2);
                                ffma2(acc2[orow][2], p[kx + 4], w2);
                            }
                        }
                    }
                }
            }
        }
    }

    __syncthreads();
    if (active) {
        const float cb = s_cb[oc];
#pragma unroll
        for (int i = 0; i < 6; i++)
#pragma unroll
            for (int jp = 0; jp < 3; jp++) {
                float2 f = up2(acc2[i][jp]);
                smem[(oc*th + prow + i)*tw + pcol + 2*jp    ] = f.x + cb;
                smem[(oc*th + prow + i)*tw + pcol + 2*jp + 1] = f.y + cb;
            }
    }
    __syncthreads();

    const int ph = th / 2, pw = tw / 2;
    const int npool = 32 * ph * pw;
    for (int i = tid; i < npool; i += 288) {
        int c = i / (ph*pw);
        int r = i % (ph*pw);
        int py = r / pw, px = r % pw;
        const float* cp = &smem[(c*th + 2*py)*tw + 2*px];
        const float* rp = &xin[(((long)b*32 + c)*132 + gy0 + 2*py)*132 + gx0 + 2*px];
        float v00 = fmaxf(cp[0]    + rp[0],     0.f);
        float v01 = fmaxf(cp[1]    + rp[1],     0.f);
        float v10 = fmaxf(cp[tw]   + rp[132],   0.f);
        float v11 = fmaxf(cp[tw+1] + rp[133],   0.f);
        float m = fmaxf(fmaxf(v00, v01), fmaxf(v10, v11));
        out[(((long)b*32 + c)*66 + ti*9 + py)*66 + tj*9 + px] = s_a2[c]*m + s_b2[c];
    }
}

// ===========================================================================
// conv2 / conv3: f32x2, (256,2) — measured-best; unchanged (profiling conv2)
// ===========================================================================
template<int CIN, int HIN, int WIN, int HOUT, int WOUT>
__global__ void __launch_bounds__(256, 2)
conv8x8_relu_kernel(const float* __restrict__ in,
                    const float* __restrict__ w,
                    const float* __restrict__ bias,
                    float* __restrict__ out) {
    __shared__ float  s_in[8*15*40];
    __shared__ float2 s_w2[8*8*64];
    const int x0 = blockIdx.x * 32, y0 = blockIdx.y * 8;
    const int b = blockIdx.z;
    const int tid = threadIdx.x;
    const int pr  = tid >> 5;
    const int s   = tid & 31;
    const int row = s >> 2;
    const int cs  = (s & 3) * 8;

    ull acc2[8];
#pragma unroll
    for (int j = 0; j < 8; j++) acc2[j] = 0ull;

    for (int chunk = 0; chunk < CIN/8; chunk++) {
        const int ic0 = chunk * 8;
        __syncthreads();
        for (int i = tid; i < 8*15*40; i += 256) {
            int icl = i / 600;
            int r = (i / 40) % 15, c = i % 40;
            int iy = y0 + r, ix = x0 + c;
            float v = 0.f;
            if (c < 39 && iy < HIN && ix < WIN)
                v = in[(((long)b*CIN + ic0 + icl)*HIN + iy)*WIN + ix];
            s_in[i] = v;
        }
        for (int i = tid; i < 8*512; i += 256) {
            int p = i >> 9;
            int r = i & 511;
            float w0 = w[(2*p    )*CIN*64 + ic0*64 + r];
            float w1 = w[(2*p + 1)*CIN*64 + ic0*64 + r];
            s_w2[i] = make_float2(w0, w1);
        }
        __syncthreads();

        for (int icl = 0; icl < 8; icl++) {
#pragma unroll
            for (int ky = 0; ky < 8; ky++) {
                const float* ip = &s_in[icl*600 + (row + ky)*40 + cs];
                float4 v0 = *(const float4*)(ip);
                float4 v1 = *(const float4*)(ip + 4);
                float4 v2 = *(const float4*)(ip + 8);
                float4 v3 = *(const float4*)(ip + 12);
                ull ivb[15];
                ivb[0]=bc2(v0.x); ivb[1]=bc2(v0.y); ivb[2]=bc2(v0.z); ivb[3]=bc2(v0.w);
                ivb[4]=bc2(v1.x); ivb[5]=bc2(v1.y); ivb[6]=bc2(v1.z); ivb[7]=bc2(v1.w);
                ivb[8]=bc2(v2.x); ivb[9]=bc2(v2.y); ivb[10]=bc2(v2.z); ivb[11]=bc2(v2.w);
                ivb[12]=bc2(v3.x); ivb[13]=bc2(v3.y); ivb[14]=bc2(v3.z);
                const float2* wrow = &s_w2[(pr*8 + icl)*64 + ky*8];
#pragma unroll
                for (int kx = 0; kx < 8; kx++) {
                    ull w2 = *(const ull*)&wrow[kx];
#pragma unroll
                    for (int j = 0; j < 8; j++)
                        ffma2(acc2[j], ivb[kx + j], w2);
                }
            }
        }
    }

    const int oy = y0 + row;
    if (oy < HOUT) {
        const int oc0 = 2*pr;
        const float b0 = bias[oc0], b1 = bias[oc0 + 1];
        float* o0 = &out[(((long)b*16 + oc0)*HOUT + oy)*WOUT];
        float* o1 = o0 + (long)HOUT*WOUT;
#pragma unroll
        for (int j = 0; j < 8; j++) {
            int ox = x0 + cs + j;
            if (ox < WOUT) {
                float2 f = up2(acc2[j]);
                o0[ox] = fmaxf(f.x + b0, 0.f);
                o1[ox] = fmaxf(f.y + b1, 0.f);
            }
        }
    }
}

// ===========================================================================
// conv4 (unchanged)
// ===========================================================================
__global__ void conv4_kernel(const float* __restrict__ in,
                             const float* __restrict__ w,
                             const float* __restrict__ bias,
                             float* __restrict__ out) {
    __shared__ float s_in[8*16*52];
    __shared__ float s_w[16*8*36];
    const int band = blockIdx.x;
    const int b = blockIdx.y;
    const int tid = threadIdx.x;
    const int ry0 = band * 6;

    float acc[9];
#pragma unroll
    for (int t = 0; t < 9; t++) acc[t] = 0.f;

    for (int chunk = 0; chunk < 2; chunk++) {
        const int ic0 = chunk * 8;
        __syncthreads();
        for (int i = tid; i < 8*16*52; i += 256) {
            int icl = i / (16*52);
            int r = (i / 52) % 16, c = i % 52;
            s_in[i] = in[(((long)b*16 + ic0 + icl)*52 + 12*band + r)*52 + c];
        }
        for (int i = tid; i < 16*8*36; i += 256) {
            int o = i / (8*36);
            int r = i % (8*36);
            int icl = r / 36, k = r % 36;
            s_w[i] = w[(o*16 + ic0 + icl)*36 + k];
        }
        __syncthreads();
#pragma unroll
        for (int t = 0; t < 9; t++) {
            int task = tid + t*256;
            if (task < 2304) {
                int oc = task / 144;
                int r = task % 144;
                int row = r / 24, cx = r % 24;
                float a = acc[t];
                for (int icl = 0; icl < 8; icl++) {
#pragma unroll
                    for (int ky = 0; ky < 6; ky++) {
                        const float* rp = &s_in[(icl*16 + 2*row + ky)*52 + 2*cx];
                        const float* wpp = &s_w[(oc*8 + icl)*36 + ky*6];
#pragma unroll
                        for (int kx = 0; kx < 6; kx++) a += rp[kx] * wpp[kx];
                    }
                }
                acc[t] = a;
            }
        }
    }
#pragma unroll
    for (int t = 0; t < 9; t++) {
        int task = tid + t*256;
        if (task < 2304) {
            int oc = task / 144;
            int r = task % 144;
            int row = r / 24, cx = r % 24;
            out[(((long)b*16 + oc)*24 + ry0 + row)*24 + cx] = fmaxf(acc[t] + bias[oc], 0.f);
        }
    }
}

// ===========================================================================
// conv5 (unchanged)
// ===========================================================================
__global__ void conv5_kernel(const float* __restrict__ in,
                             const float* __restrict__ w,
                             const float* __restrict__ bias,
                             float* __restrict__ out) {
    __shared__ float s_in[16*14*24];
    __shared__ float s_w[16*16*25];
    const int band = blockIdx.x;
    const int b = blockIdx.y;
    const int tid = threadIdx.x;
    const int ry0 = band * 10;

    for (int i = tid; i < 16*14*24; i += 256) {
        int icl = i / (14*24);
        int r = (i / 24) % 14, c = i % 24;
        s_in[i] = in[(((long)b*16 + icl)*24 + ry0 + r)*24 + c];
    }
    for (int i = tid; i < 16*16*25; i += 256)
        s_w[i] = w[i];
    __syncthreads();

#pragma unroll
    for (int t = 0; t < 13; t++) {
        int task = tid + t*256;
        if (task < 3200) {
            int oc = task / 200;
            int r = task % 200;
            int row = r / 20, cx = r % 20;
            float a = 0.f;
            for (int ic = 0; ic < 16; ic++) {
#pragma unroll
                for (int ky = 0; ky < 5; ky++) {
                    const float* rp = &s_in[(ic*14 + row + ky)*24 + cx];
                    const float* wpp = &s_w[(oc*16 + ic)*25 + ky*5];
#pragma unroll
                    for (int kx = 0; kx < 5; kx++) a += rp[kx] * wpp[kx];
                }
            }
            out[(((long)b*16 + oc)*20 + ry0 + row)*20 + cx] = fmaxf(a + bias[oc], 0.f);
        }
    }
}

// ===========================================================================
// GEMM for fc1/fc2: NOW f32x2 — pack adjacent n-pairs (bitwise-identical
// accumulation order). Per k: 1 LDS.128 (a) + 2 LDS.64 (b) + 4 bc2 + 8 ffma2.
// ===========================================================================
__global__ void __launch_bounds__(256)
gemm_relu_kernel(const float* __restrict__ X,
                 const float* __restrict__ W,
                 const float* __restrict__ bias,
                 float* __restrict__ out,
                 int N, int K) {
    __shared__ float xs[64][68];
    __shared__ float ws[64][68];
    const int n0 = blockIdx.x * 64;
    const int tid = threadIdx.x;
    const int tx = tid & 15, ty = tid >> 4;

    ull acc2[4][2];
#pragma unroll
    for (int i = 0; i < 4; i++)
#pragma unroll
        for (int j = 0; j < 2; j++) acc2[i][j] = 0ull;

    for (int k0 = 0; k0 < K; k0 += 64) {
        __syncthreads();
        for (int i = tid; i < 64*64; i += 256) {
            int m = i >> 6, k = i & 63;
            xs[k][m] = X[m*K + k0 + k];
        }
        for (int i = tid; i < 64*64; i += 256) {
            int n = i >> 6, k = i & 63;
            ws[k][n] = W[(long)(n0 + n)*K + k0 + k];
        }
        __syncthreads();
#pragma unroll 8
        for (int k = 0; k < 64; k++) {
            float4 a4 = *(const float4*)&xs[k][ty*4];
            ull b0 = *(const ull*)&ws[k][tx*4];
            ull b1 = *(const ull*)&ws[k][tx*4 + 2];
            ull a0 = bc2(a4.x), a1 = bc2(a4.y), a2 = bc2(a4.z), a3 = bc2(a4.w);
            ffma2(acc2[0][0], a0, b0); ffma2(acc2[0][1], a0, b1);
            ffma2(acc2[1][0], a1, b0); ffma2(acc2[1][1], a1, b1);
            ffma2(acc2[2][0], a2, b0); ffma2(acc2[2][1], a2, b1);
            ffma2(acc2[3][0], a3, b0); ffma2(acc2[3][1], a3, b1);
        }
    }
#pragma unroll
    for (int i = 0; i < 4; i++) {
        int m = ty*4 + i;
#pragma unroll
        for (int j = 0; j < 2; j++) {
            int n = n0 + tx*4 + 2*j;
            float2 f = up2(acc2[i][j]);
            out[m*N + n]     = fmaxf(f.x + bias[n],     0.f);
            out[m*N + n + 1] = fmaxf(f.y + bias[n + 1], 0.f);
        }
    }
}

// ===========================================================================
// fc3 (unchanged)
// ===========================================================================
__global__ void fc3_kernel(const float* __restrict__ X,
                           const float* __restrict__ W,
                           const float* __restrict__ bias,
                           float* __restrict__ out) {
    const int warp = (blockIdx.x * 256 + threadIdx.x) >> 5;
    const int lane = threadIdx.x & 31;
    if (warp >= 768) return;
    const int m = warp / 12, n = warp % 12;
    float s = 0.f;
    for (int k = lane; k < 2048; k += 32)
        s += X[m*2048 + k] * W[n*2048 + k];
#pragma unroll
    for (int o = 16; o; o >>= 1) s += __shfl_xor_sync(0xFFFFFFFFu, s, o);
    if (lane == 0) out[m*12 + n] = s + bias[n];
}

// ===========================================================================
extern "C" void kernel_launch(void* const* d_in, const int* in_sizes, int n_in,
                              void* d_out, int out_size) {
    const float* x       = (const float*)d_in[0];
    const float* conv1_w = (const float*)d_in[1];
    const float* conv1_b = (const float*)d_in[2];
    const float* rg_g    = (const float*)d_in[3];
    const float* rg_b    = (const float*)d_in[4];
    const float* rg_m    = (const float*)d_in[5];
    const float* rg_v    = (const float*)d_in[6];
    const float* rg_w    = (const float*)d_in[7];
    const float* rg_cb   = (const float*)d_in[8];
    const float* bn2_g   = (const float*)d_in[9];
    const float* bn2_b   = (const float*)d_in[10];
    const float* bn2_m   = (const float*)d_in[11];
    const float* bn2_v   = (const float*)d_in[12];
    const float* conv2_w = (const float*)d_in[13];
    const float* conv2_b = (const float*)d_in[14];
    const float* conv3_w = (const float*)d_in[15];
    const float* conv3_b = (const float*)d_in[16];
    const float* conv4_w = (const float*)d_in[17];
    const float* conv4_b = (const float*)d_in[18];
    const float* conv5_w = (const float*)d_in[19];
    const float* conv5_b = (const float*)d_in[20];
    const float* fc1_w   = (const float*)d_in[21];
    const float* fc1_b   = (const float*)d_in[22];
    const float* fc2_w   = (const float*)d_in[23];
    const float* fc2_b   = (const float*)d_in[24];
    const float* fc3_w   = (const float*)d_in[25];
    const float* fc3_b   = (const float*)d_in[26];

    float *b1, *b2, *b3, *b4, *b5, *b6, *f1, *f2, *dm;
    cudaGetSymbolAddress((void**)&b1, g_buf1);
    cudaGetSymbolAddress((void**)&b2, g_buf2);
    cudaGetSymbolAddress((void**)&b3, g_buf3);
    cudaGetSymbolAddress((void**)&b4, g_buf4);
    cudaGetSymbolAddress((void**)&b5, g_buf5);
    cudaGetSymbolAddress((void**)&b6, g_buf6);
    cudaGetSymbolAddress((void**)&f1, g_fc1o);
    cudaGetSymbolAddress((void**)&f2, g_fc2o);
    cudaGetSymbolAddress((void**)&dm, g_dummy);

    // one tiny launch: ncu fixed-index capture (4th launch) lands on conv2
    nudge_kernel<<<1, 32>>>(dm);

    conv1_kernel<<<dim3(12, 8, 64), 264>>>(x, conv1_w, conv1_b, b1);
    region_kernel<<<dim3(64, 64), 288>>>(b1, rg_g, rg_b, rg_m, rg_v, rg_w, rg_cb,
                                         bn2_g, bn2_b, bn2_m, bn2_v, b2);
    conv8x8_relu_kernel<32, 66, 66, 59, 59><<<dim3(2, 8, 64), 256>>>(b2, conv2_w, conv2_b, b3);
    conv8x8_relu_kernel<16, 59, 59, 52, 52><<<dim3(2, 7, 64), 256>>>(b3, conv3_w, conv3_b, b4);
    conv4_kernel<<<dim3(4, 64), 256>>>(b4, conv4_w, conv4_b, b5);
    conv5_kernel<<<dim3(2, 64), 256>>>(b5, conv5_w, conv5_b, b6);
    gemm_relu_kernel<<<64, 256>>>(b6, fc1_w, fc1_b, f1, 4096, 6400);
    gemm_relu_kernel<<<32, 256>>>(f1, fc2_w, fc2_b, f2, 2048, 4096);
    fc3_kernel<<<96, 256>>>(f2, fc3_w, fc3_b, (float*)d_out);
}

// round 14
// speedup vs baseline: 1.2632x; 1.2297x over previous
#include <cuda_runtime.h>
#include <cuda_bf16.h>
#include <cstdint>

typedef unsigned long long ull;

// ---- packed f32x2 helpers -------------------------------------------------
__device__ __forceinline__ ull pk2(float lo, float hi) {
    ull r; asm("mov.b64 %0, {%1, %2};" : "=l"(r) : "f"(lo), "f"(hi)); return r;
}
__device__ __forceinline__ ull bc2(float v) { return pk2(v, v); }
__device__ __forceinline__ void ffma2(ull& d, ull a, ull b) {
    asm("fma.rn.f32x2 %0, %1, %2, %3;" : "=l"(d) : "l"(a), "l"(b), "l"(d));
}
__device__ __forceinline__ float2 up2(ull v) {
    float2 f; asm("mov.b64 {%0, %1}, %2;" : "=f"(f.x), "=f"(f.y) : "l"(v)); return f;
}

// ---------------- scratch buffers ------------------------------------------
__device__ float g_buf1[64u*32u*132u*132u]; // conv1 out
__device__ float g_buf2[64u*32u*66u*66u];   // region+pool+bn2 out
__device__ float g_buf3[64u*16u*59u*59u];   // conv2 out
__device__ float g_buf4[64u*16u*52u*52u];   // conv3 out
__device__ float g_buf5[64u*16u*24u*24u];   // conv4 out
__device__ float g_buf6[64u*16u*20u*20u];   // conv5 out (fc input)
__device__ float g_fc1o[64u*4096u];
__device__ float g_fc2o[64u*2048u];
__device__ float g_part[4u*64u*4096u];      // split-K partials (4 MB)
__device__ float g_dummy[32];

// dummy launch: land the ncu fixed-index capture window (4th launch) on conv2
__global__ void nudge_kernel(float* p) { p[threadIdx.x] = 0.f; }

// ===========================================================================
// conv1 (round-4 f32x2) — at ~99% of the FFMA2-pipe limit, do not touch.
// ===========================================================================
__global__ void __launch_bounds__(264, 2)
conv1_kernel(const float* __restrict__ x,
             const float* __restrict__ w,
             const float* __restrict__ bias,
             float* __restrict__ out) {
    __shared__ float  s_in[3*32*76];
    __shared__ float2 s_w2[2*363];
    const int t   = blockIdx.x;
    const int ti  = t >> 1, tj = t & 1;
    const int gy0 = ti * 22, gx0 = tj * 66;
    const int ocg = blockIdx.y;
    const int b   = blockIdx.z;
    const int tid = threadIdx.x;

    for (int i = tid; i < 2*363; i += 264) {
        int h = i / 363, idx = i % 363;
        int oc = ocg*4 + h*2;
        s_w2[i] = make_float2(w[oc*363 + idx], w[(oc+1)*363 + idx]);
    }
    for (int i = tid; i < 3*32*76; i += 264) {
        int c  = i / 2432;
        int r  = (i / 76) % 32, cc = i % 76;
        s_in[i] = x[((b*3 + c)*142 + gy0 + r)*142 + gx0 + cc];
    }
    __syncthreads();

    const int half = tid / 132;
    const int s    = tid % 132;
    const int row  = s / 6;
    const int cs   = (s % 6) * 11;

    ull acc2[11];
#pragma unroll
    for (int j = 0; j < 11; j++) acc2[j] = 0ull;

    for (int c = 0; c < 3; c++) {
        for (int ky = 0; ky < 11; ky++) {
            const float* ip = &s_in[c*2432 + (row + ky)*76 + cs];
            ull ivb[21];
#pragma unroll
            for (int j = 0; j < 21; j++) ivb[j] = bc2(ip[j]);
            const float2* wrow = &s_w2[half*363 + c*121 + ky*11];
#pragma unroll
            for (int kx = 0; kx < 11; kx++) {
                ull w2 = *(const ull*)&wrow[kx];
#pragma unroll
                for (int j = 0; j < 11; j++)
                    ffma2(acc2[j], ivb[kx + j], w2);
            }
        }
    }
    const int oc = ocg*4 + half*2;
    const float b0 = bias[oc], b1 = bias[oc+1];
    float* o0 = &out[(((long)b*32 + oc)*132 + gy0 + row)*132 + gx0 + cs];
    float* o1 = o0 + 132*132;
#pragma unroll
    for (int j = 0; j < 11; j++) {
        float2 f = up2(acc2[j]);
        o0[j] = f.x + b0;
        o1[j] = f.y + b1;
    }
}

// ===========================================================================
// region layer fused — round-11 version (measured best).
// ===========================================================================
__global__ void __launch_bounds__(288)
region_kernel(const float* __restrict__ xin,
              const float* __restrict__ rg_g, const float* __restrict__ rg_b,
              const float* __restrict__ rg_m, const float* __restrict__ rg_v,
              const float* __restrict__ rg_w, const float* __restrict__ rg_cb,
              const float* __restrict__ bn2_g, const float* __restrict__ bn2_b,
              const float* __restrict__ bn2_m, const float* __restrict__ bn2_v,
              float* __restrict__ out) {
    __shared__ float smem[11152];
    __shared__ float s_scale[32], s_shift[32], s_cb[32], s_a2[32], s_b2[32];

    const int tile = blockIdx.x;
    const int b    = blockIdx.y;
    const int ti = tile >> 3, tj = tile & 7;
    const int th = (ti < 7) ? 18 : 6, tw = (tj < 7) ? 18 : 6;
    const int gy0 = ti * 18, gx0 = tj * 18;
    const int tid = threadIdx.x;

    if (tid < 32) {
        int p = tile*32 + tid;
        float a = rg_g[p] * rsqrtf(rg_v[p] + 1e-5f);
        s_scale[tid] = a;
        s_shift[tid] = rg_b[p] - rg_m[p]*a;
        s_cb[tid]    = rg_cb[p];
    } else if (tid < 64) {
        int c = tid - 32;
        float a2 = bn2_g[c] * rsqrtf(bn2_v[c] + 1e-5f);
        s_a2[c] = a2;
        s_b2[c] = bn2_b[c] - bn2_m[c]*a2;
    }

    const int hp = th + 2, wp = tw + 2;
    const int npx = tw / 6, npy = th / 6;
    const int pos = tid >> 5;
    const int oc  = tid & 31;
    const bool active = pos < npx * npy;
    const int prow = (pos / npx) * 6;
    const int pcol = (pos % npx) * 6;

    float* s_in = smem;
    float* s_w  = smem + 6400;

    ull acc2[6][3];
#pragma unroll
    for (int i = 0; i < 6; i++)
#pragma unroll
        for (int j = 0; j < 3; j++) acc2[i][j] = 0ull;

    for (int chunk = 0; chunk < 2; chunk++) {
        const int ic0 = chunk * 16;
        __syncthreads();
        const int nin = 16 * hp * wp;
        for (int i = tid; i < nin; i += 288) {
            int icl = i / (hp*wp);
            int r = i % (hp*wp);
            int y = r / wp, xx = r % wp;
            float v = 0.f;
            if (y > 0 && y < hp-1 && xx > 0 && xx < wp-1) {
                float raw = xin[(((long)b*32 + ic0 + icl)*132 + gy0 + y - 1)*132 + gx0 + xx - 1];
                v = fmaxf(s_scale[ic0+icl]*raw + s_shift[ic0+icl], 0.f);
            }
            s_in[i] = v;
        }
        for (int i = tid; i < 32*144; i += 288) {
            int o  = i / 144;
            int kk = i % 144;
            s_w[kk*33 + o] = rg_w[(long)tile*9216 + o*288 + ic0*9 + kk];
        }
        __syncthreads();

        if (active) {
            for (int icl = 0; icl < 16; icl++) {
                ull wr2[9];
#pragma unroll
                for (int k = 0; k < 9; k++) wr2[k] = bc2(s_w[(icl*9 + k)*33 + oc]);
                const float* ib = &s_in[icl*hp*wp + prow*wp + pcol];
#pragma unroll
                for (int r = 0; r < 8; r++) {
                    float iv[8];
#pragma unroll
                    for (int j = 0; j < 8; j++) iv[j] = ib[r*wp + j];
                    ull p[7];
#pragma unroll
                    for (int i = 0; i < 7; i++) p[i] = pk2(iv[i], iv[i+1]);
#pragma unroll
                    for (int ky = 0; ky < 3; ky++) {
                        int orow = r - ky;
                        if (orow >= 0 && orow < 6) {
#pragma unroll
                            for (int kx = 0; kx < 3; kx++) {
                                ull w2 = wr2[ky*3 + kx];
                                ffma2(acc2[orow][0], p[kx    ], w2);
                                ffma2(acc2[orow][1], p[kx + 2], w2);
                                ffma2(acc2[orow][2], p[kx + 4], w2);
                            }
                        }
                    }
                }
            }
        }
    }

    __syncthreads();
    if (active) {
        const float cb = s_cb[oc];
#pragma unroll
        for (int i = 0; i < 6; i++)
#pragma unroll
            for (int jp = 0; jp < 3; jp++) {
                float2 f = up2(acc2[i][jp]);
                smem[(oc*th + prow + i)*tw + pcol + 2*jp    ] = f.x + cb;
                smem[(oc*th + prow + i)*tw + pcol + 2*jp + 1] = f.y + cb;
            }
    }
    __syncthreads();

    const int ph = th / 2, pw = tw / 2;
    const int npool = 32 * ph * pw;
    for (int i = tid; i < npool; i += 288) {
        int c = i / (ph*pw);
        int r = i % (ph*pw);
        int py = r / pw, px = r % pw;
        const float* cp = &smem[(c*th + 2*py)*tw + 2*px];
        const float* rp = &xin[(((long)b*32 + c)*132 + gy0 + 2*py)*132 + gx0 + 2*px];
        float v00 = fmaxf(cp[0]    + rp[0],     0.f);
        float v01 = fmaxf(cp[1]    + rp[1],     0.f);
        float v10 = fmaxf(cp[tw]   + rp[132],   0.f);
        float v11 = fmaxf(cp[tw+1] + rp[133],   0.f);
        float m = fmaxf(fmaxf(v00, v01), fmaxf(v10, v11));
        out[(((long)b*32 + c)*66 + ti*9 + py)*66 + tj*9 + px] = s_a2[c]*m + s_b2[c];
    }
}

// ===========================================================================
// conv2 / conv3: kx-loop split into 2 halves, ivb[12] reused — organic reg
// trim (goal: <=80 regs -> 3 blocks/SM). FMA order identical to before.
// ===========================================================================
template<int CIN, int HIN, int WIN, int HOUT, int WOUT>
__global__ void __launch_bounds__(256, 2)
conv8x8_relu_kernel(const float* __restrict__ in,
                    const float* __restrict__ w,
                    const float* __restrict__ bias,
                    float* __restrict__ out) {
    __shared__ float  s_in[8*15*40];
    __shared__ float2 s_w2[8*8*64];
    const int x0 = blockIdx.x * 32, y0 = blockIdx.y * 8;
    const int b = blockIdx.z;
    const int tid = threadIdx.x;
    const int pr  = tid >> 5;
    const int s   = tid & 31;
    const int row = s >> 2;
    const int cs  = (s & 3) * 8;

    ull acc2[8];
#pragma unroll
    for (int j = 0; j < 8; j++) acc2[j] = 0ull;

    for (int chunk = 0; chunk < CIN/8; chunk++) {
        const int ic0 = chunk * 8;
        __syncthreads();
        for (int i = tid; i < 8*15*40; i += 256) {
            int icl = i / 600;
            int r = (i / 40) % 15, c = i % 40;
            int iy = y0 + r, ix = x0 + c;
            float v = 0.f;
            if (c < 39 && iy < HIN && ix < WIN)
                v = in[(((long)b*CIN + ic0 + icl)*HIN + iy)*WIN + ix];
            s_in[i] = v;
        }
        for (int i = tid; i < 8*512; i += 256) {
            int p = i >> 9;
            int r = i & 511;
            float w0 = w[(2*p    )*CIN*64 + ic0*64 + r];
            float w1 = w[(2*p + 1)*CIN*64 + ic0*64 + r];
            s_w2[i] = make_float2(w0, w1);
        }
        __syncthreads();

        for (int icl = 0; icl < 8; icl++) {
#pragma unroll
            for (int ky = 0; ky < 8; ky++) {
                const float* ip = &s_in[icl*600 + (row + ky)*40 + cs];
                const float2* wrow = &s_w2[(pr*8 + icl)*64 + ky*8];
#pragma unroll
                for (int h = 0; h < 2; h++) {
                    float4 v0 = *(const float4*)(ip + h*4);
                    float4 v1 = *(const float4*)(ip + h*4 + 4);
                    float4 v2 = *(const float4*)(ip + h*4 + 8);
                    ull ivb[12];
                    ivb[0]=bc2(v0.x);  ivb[1]=bc2(v0.y);  ivb[2]=bc2(v0.z);  ivb[3]=bc2(v0.w);
                    ivb[4]=bc2(v1.x);  ivb[5]=bc2(v1.y);  ivb[6]=bc2(v1.z);  ivb[7]=bc2(v1.w);
                    ivb[8]=bc2(v2.x);  ivb[9]=bc2(v2.y);  ivb[10]=bc2(v2.z); ivb[11]=bc2(v2.w);
#pragma unroll
                    for (int kx = 0; kx < 4; kx++) {
                        ull w2 = *(const ull*)&wrow[h*4 + kx];
#pragma unroll
                        for (int j = 0; j < 8; j++)
                            ffma2(acc2[j], ivb[kx + j], w2);
                    }
                }
            }
        }
    }

    const int oy = y0 + row;
    if (oy < HOUT) {
        const int oc0 = 2*pr;
        const float b0 = bias[oc0], b1 = bias[oc0 + 1];
        float* o0 = &out[(((long)b*16 + oc0)*HOUT + oy)*WOUT];
        float* o1 = o0 + (long)HOUT*WOUT;
#pragma unroll
        for (int j = 0; j < 8; j++) {
            int ox = x0 + cs + j;
            if (ox < WOUT) {
                float2 f = up2(acc2[j]);
                o0[ox] = fmaxf(f.x + b0, 0.f);
                o1[ox] = fmaxf(f.y + b1, 0.f);
            }
        }
    }
}

// ===========================================================================
// conv4 (unchanged)
// ===========================================================================
__global__ void conv4_kernel(const float* __restrict__ in,
                             const float* __restrict__ w,
                             const float* __restrict__ bias,
                             float* __restrict__ out) {
    __shared__ float s_in[8*16*52];
    __shared__ float s_w[16*8*36];
    const int band = blockIdx.x;
    const int b = blockIdx.y;
    const int tid = threadIdx.x;
    const int ry0 = band * 6;

    float acc[9];
#pragma unroll
    for (int t = 0; t < 9; t++) acc[t] = 0.f;

    for (int chunk = 0; chunk < 2; chunk++) {
        const int ic0 = chunk * 8;
        __syncthreads();
        for (int i = tid; i < 8*16*52; i += 256) {
            int icl = i / (16*52);
            int r = (i / 52) % 16, c = i % 52;
            s_in[i] = in[(((long)b*16 + ic0 + icl)*52 + 12*band + r)*52 + c];
        }
        for (int i = tid; i < 16*8*36; i += 256) {
            int o = i / (8*36);
            int r = i % (8*36);
            int icl = r / 36, k = r % 36;
            s_w[i] = w[(o*16 + ic0 + icl)*36 + k];
        }
        __syncthreads();
#pragma unroll
        for (int t = 0; t < 9; t++) {
            int task = tid + t*256;
            if (task < 2304) {
                int oc = task / 144;
                int r = task % 144;
                int row = r / 24, cx = r % 24;
                float a = acc[t];
                for (int icl = 0; icl < 8; icl++) {
#pragma unroll
                    for (int ky = 0; ky < 6; ky++) {
                        const float* rp = &s_in[(icl*16 + 2*row + ky)*52 + 2*cx];
                        const float* wpp = &s_w[(oc*8 + icl)*36 + ky*6];
#pragma unroll
                        for (int kx = 0; kx < 6; kx++) a += rp[kx] * wpp[kx];
                    }
                }
                acc[t] = a;
            }
        }
    }
#pragma unroll
    for (int t = 0; t < 9; t++) {
        int task = tid + t*256;
        if (task < 2304) {
            int oc = task / 144;
            int r = task % 144;
            int row = r / 24, cx = r % 24;
            out[(((long)b*16 + oc)*24 + ry0 + row)*24 + cx] = fmaxf(acc[t] + bias[oc], 0.f);
        }
    }
}

// ===========================================================================
// conv5 (unchanged)
// ===========================================================================
__global__ void conv5_kernel(const float* __restrict__ in,
                             const float* __restrict__ w,
                             const float* __restrict__ bias,
                             float* __restrict__ out) {
    __shared__ float s_in[16*14*24];
    __shared__ float s_w[16*16*25];
    const int band = blockIdx.x;
    const int b = blockIdx.y;
    const int tid = threadIdx.x;
    const int ry0 = band * 10;

    for (int i = tid; i < 16*14*24; i += 256) {
        int icl = i / (14*24);
        int r = (i / 24) % 14, c = i % 24;
        s_in[i] = in[(((long)b*16 + icl)*24 + ry0 + r)*24 + c];
    }
    for (int i = tid; i < 16*16*25; i += 256)
        s_w[i] = w[i];
    __syncthreads();

#pragma unroll
    for (int t = 0; t < 13; t++) {
        int task = tid + t*256;
        if (task < 3200) {
            int oc = task / 200;
            int r = task % 200;
            int row = r / 20, cx = r % 20;
            float a = 0.f;
            for (int ic = 0; ic < 16; ic++) {
#pragma unroll
                for (int ky = 0; ky < 5; ky++) {
                    const float* rp = &s_in[(ic*14 + row + ky)*24 + cx];
                    const float* wpp = &s_w[(oc*16 + ic)*25 + ky*5];
#pragma unroll
                    for (int kx = 0; kx < 5; kx++) a += rp[kx] * wpp[kx];
                }
            }
            out[(((long)b*16 + oc)*20 + ry0 + row)*20 + cx] = fmaxf(a + bias[oc], 0.f);
        }
    }
}

// ===========================================================================
// split-K GEMM for fc1/fc2: part[s][64][N] = X[:, ks:ks+Kc] @ W[:, ks:ks+Kc]^T
// grid (N/64, S). f32x2 inner loop (order within a split unchanged).
// ===========================================================================
__global__ void __launch_bounds__(256)
gemm_splitk_kernel(const float* __restrict__ X,
                   const float* __restrict__ W,
                   float* __restrict__ part,
                   int N, int K, int Kc) {
    __shared__ float xs[64][68];
    __shared__ float ws[64][68];
    const int n0 = blockIdx.x * 64;
    const int ks = blockIdx.y * Kc;
    const int tid = threadIdx.x;
    const int tx = tid & 15, ty = tid >> 4;

    ull acc2[4][2];
#pragma unroll
    for (int i = 0; i < 4; i++)
#pragma unroll
        for (int j = 0; j < 2; j++) acc2[i][j] = 0ull;

    for (int k0 = ks; k0 < ks + Kc; k0 += 64) {
        __syncthreads();
        for (int i = tid; i < 64*64; i += 256) {
            int m = i >> 6, k = i & 63;
            xs[k][m] = X[m*K + k0 + k];
        }
        for (int i = tid; i < 64*64; i += 256) {
            int n = i >> 6, k = i & 63;
            ws[k][n] = W[(long)(n0 + n)*K + k0 + k];
        }
        __syncthreads();
#pragma unroll 8
        for (int k = 0; k < 64; k++) {
            float4 a4 = *(const float4*)&xs[k][ty*4];
            ull b0 = *(const ull*)&ws[k][tx*4];
            ull b1 = *(const ull*)&ws[k][tx*4 + 2];
            ull a0 = bc2(a4.x), a1 = bc2(a4.y), a2 = bc2(a4.z), a3 = bc2(a4.w);
            ffma2(acc2[0][0], a0, b0); ffma2(acc2[0][1], a0, b1);
            ffma2(acc2[1][0], a1, b0); ffma2(acc2[1][1], a1, b1);
            ffma2(acc2[2][0], a2, b0); ffma2(acc2[2][1], a2, b1);
            ffma2(acc2[3][0], a3, b0); ffma2(acc2[3][1], a3, b1);
        }
    }
    float* pb = part + (long)blockIdx.y * 64 * N;
#pragma unroll
    for (int i = 0; i < 4; i++) {
        int m = ty*4 + i;
#pragma unroll
        for (int j = 0; j < 2; j++) {
            int n = n0 + tx*4 + 2*j;
            float2 f = up2(acc2[i][j]);
            pb[m*N + n]     = f.x;
            pb[m*N + n + 1] = f.y;
        }
    }
}

// fuse: out = relu(sum_s part[s] + bias)
__global__ void fc_reduce_kernel(const float* __restrict__ part,
                                 const float* __restrict__ bias,
                                 float* __restrict__ out, int N) {
    int i = blockIdx.x * 256 + threadIdx.x;
    if (i >= 64 * N) return;
    int n = i % N;
    float s = part[i] + part[64*N + i] + part[2*64*N + i] + part[3*64*N + i];
    out[i] = fmaxf(s + bias[n], 0.f);
}

// ===========================================================================
// fc3 (unchanged)
// ===========================================================================
__global__ void fc3_kernel(const float* __restrict__ X,
                           const float* __restrict__ W,
                           const float* __restrict__ bias,
                           float* __restrict__ out) {
    const int warp = (blockIdx.x * 256 + threadIdx.x) >> 5;
    const int lane = threadIdx.x & 31;
    if (warp >= 768) return;
    const int m = warp / 12, n = warp % 12;
    float s = 0.f;
    for (int k = lane; k < 2048; k += 32)
        s += X[m*2048 + k] * W[n*2048 + k];
#pragma unroll
    for (int o = 16; o; o >>= 1) s += __shfl_xor_sync(0xFFFFFFFFu, s, o);
    if (lane == 0) out[m*12 + n] = s + bias[n];
}

// ===========================================================================
extern "C" void kernel_launch(void* const* d_in, const int* in_sizes, int n_in,
                              void* d_out, int out_size) {
    const float* x       = (const float*)d_in[0];
    const float* conv1_w = (const float*)d_in[1];
    const float* conv1_b = (const float*)d_in[2];
    const float* rg_g    = (const float*)d_in[3];
    const float* rg_b    = (const float*)d_in[4];
    const float* rg_m    = (const float*)d_in[5];
    const float* rg_v    = (const float*)d_in[6];
    const float* rg_w    = (const float*)d_in[7];
    const float* rg_cb   = (const float*)d_in[8];
    const float* bn2_g   = (const float*)d_in[9];
    const float* bn2_b   = (const float*)d_in[10];
    const float* bn2_m   = (const float*)d_in[11];
    const float* bn2_v   = (const float*)d_in[12];
    const float* conv2_w = (const float*)d_in[13];
    const float* conv2_b = (const float*)d_in[14];
    const float* conv3_w = (const float*)d_in[15];
    const float* conv3_b = (const float*)d_in[16];
    const float* conv4_w = (const float*)d_in[17];
    const float* conv4_b = (const float*)d_in[18];
    const float* conv5_w = (const float*)d_in[19];
    const float* conv5_b = (const float*)d_in[20];
    const float* fc1_w   = (const float*)d_in[21];
    const float* fc1_b   = (const float*)d_in[22];
    const float* fc2_w   = (const float*)d_in[23];
    const float* fc2_b   = (const float*)d_in[24];
    const float* fc3_w   = (const float*)d_in[25];
    const float* fc3_b   = (const float*)d_in[26];

    float *b1, *b2, *b3, *b4, *b5, *b6, *f1, *f2, *pp, *dm;
    cudaGetSymbolAddress((void**)&b1, g_buf1);
    cudaGetSymbolAddress((void**)&b2, g_buf2);
    cudaGetSymbolAddress((void**)&b3, g_buf3);
    cudaGetSymbolAddress((void**)&b4, g_buf4);
    cudaGetSymbolAddress((void**)&b5, g_buf5);
    cudaGetSymbolAddress((void**)&b6, g_buf6);
    cudaGetSymbolAddress((void**)&f1, g_fc1o);
    cudaGetSymbolAddress((void**)&f2, g_fc2o);
    cudaGetSymbolAddress((void**)&pp, g_part);
    cudaGetSymbolAddress((void**)&dm, g_dummy);

    // one tiny launch: ncu fixed-index capture (4th launch) lands on conv2
    nudge_kernel<<<1, 32>>>(dm);

    conv1_kernel<<<dim3(12, 8, 64), 264>>>(x, conv1_w, conv1_b, b1);
    region_kernel<<<dim3(64, 64), 288>>>(b1, rg_g, rg_b, rg_m, rg_v, rg_w, rg_cb,
                                         bn2_g, bn2_b, bn2_m, bn2_v, b2);
    conv8x8_relu_kernel<32, 66, 66, 59, 59><<<dim3(2, 8, 64), 256>>>(b2, conv2_w, conv2_b, b3);
    conv8x8_relu_kernel<16, 59, 59, 52, 52><<<dim3(2, 7, 64), 256>>>(b3, conv3_w, conv3_b, b4);
    conv4_kernel<<<dim3(4, 64), 256>>>(b4, conv4_w, conv4_b, b5);
    conv5_kernel<<<dim3(2, 64), 256>>>(b5, conv5_w, conv5_b, b6);
    // fc1: split-K S=4 (Kc=1600), then fuse
    gemm_splitk_kernel<<<dim3(64, 4), 256>>>(b6, fc1_w, pp, 4096, 6400, 1600);
    fc_reduce_kernel<<<(64*4096 + 255)/256, 256>>>(pp, fc1_b, f1, 4096);
    // fc2: split-K S=4 (Kc=1024), then fuse
    gemm_splitk_kernel<<<dim3(32, 4), 256>>>(f1, fc2_w, pp, 2048, 4096, 1024);
    fc_reduce_kernel<<<(64*2048 + 255)/256, 256>>>(pp, fc2_b, f2, 2048);
    fc3_kernel<<<96, 256>>>(f2, fc3_w, fc3_b, (float*)d_out);
}

// round 15
// speedup vs baseline: 1.3461x; 1.0656x over previous
#include <cuda_runtime.h>
#include <cuda_bf16.h>
#include <cstdint>

typedef unsigned long long ull;

// ---- packed f32x2 helpers -------------------------------------------------
__device__ __forceinline__ ull pk2(float lo, float hi) {
    ull r; asm("mov.b64 %0, {%1, %2};" : "=l"(r) : "f"(lo), "f"(hi)); return r;
}
__device__ __forceinline__ ull bc2(float v) { return pk2(v, v); }
__device__ __forceinline__ void ffma2(ull& d, ull a, ull b) {
    asm("fma.rn.f32x2 %0, %1, %2, %3;" : "=l"(d) : "l"(a), "l"(b), "l"(d));
}
__device__ __forceinline__ float2 up2(ull v) {
    float2 f; asm("mov.b64 {%0, %1}, %2;" : "=f"(f.x), "=f"(f.y) : "l"(v)); return f;
}

// ---------------- scratch buffers ------------------------------------------
__device__ float g_buf1[64u*32u*132u*132u]; // conv1 out
__device__ float g_buf2[64u*32u*66u*66u];   // region+pool+bn2 out
__device__ float g_buf3[64u*16u*59u*59u];   // conv2 out
__device__ float g_buf4[64u*16u*52u*52u];   // conv3 out
__device__ float g_buf5[64u*16u*24u*24u];   // conv4 out
__device__ float g_buf6[64u*16u*20u*20u];   // conv5 out (fc input)
__device__ float g_fc1o[64u*4096u];
__device__ float g_fc2o[64u*2048u];
__device__ float g_part[4u*64u*4096u];      // split-K partials (4 MB)
__device__ float g_dummy[32];

// dummy launch: land the ncu fixed-index capture window (4th launch) on conv2
__global__ void nudge_kernel(float* p) { p[threadIdx.x] = 0.f; }

// ===========================================================================
// conv1 (round-4 f32x2) — at ~99% of the FFMA2-pipe limit, do not touch.
// ===========================================================================
__global__ void __launch_bounds__(264, 2)
conv1_kernel(const float* __restrict__ x,
             const float* __restrict__ w,
             const float* __restrict__ bias,
             float* __restrict__ out) {
    __shared__ float  s_in[3*32*76];
    __shared__ float2 s_w2[2*363];
    const int t   = blockIdx.x;
    const int ti  = t >> 1, tj = t & 1;
    const int gy0 = ti * 22, gx0 = tj * 66;
    const int ocg = blockIdx.y;
    const int b   = blockIdx.z;
    const int tid = threadIdx.x;

    for (int i = tid; i < 2*363; i += 264) {
        int h = i / 363, idx = i % 363;
        int oc = ocg*4 + h*2;
        s_w2[i] = make_float2(w[oc*363 + idx], w[(oc+1)*363 + idx]);
    }
    for (int i = tid; i < 3*32*76; i += 264) {
        int c  = i / 2432;
        int r  = (i / 76) % 32, cc = i % 76;
        s_in[i] = x[((b*3 + c)*142 + gy0 + r)*142 + gx0 + cc];
    }
    __syncthreads();

    const int half = tid / 132;
    const int s    = tid % 132;
    const int row  = s / 6;
    const int cs   = (s % 6) * 11;

    ull acc2[11];
#pragma unroll
    for (int j = 0; j < 11; j++) acc2[j] = 0ull;

    for (int c = 0; c < 3; c++) {
        for (int ky = 0; ky < 11; ky++) {
            const float* ip = &s_in[c*2432 + (row + ky)*76 + cs];
            ull ivb[21];
#pragma unroll
            for (int j = 0; j < 21; j++) ivb[j] = bc2(ip[j]);
            const float2* wrow = &s_w2[half*363 + c*121 + ky*11];
#pragma unroll
            for (int kx = 0; kx < 11; kx++) {
                ull w2 = *(const ull*)&wrow[kx];
#pragma unroll
                for (int j = 0; j < 11; j++)
                    ffma2(acc2[j], ivb[kx + j], w2);
            }
        }
    }
    const int oc = ocg*4 + half*2;
    const float b0 = bias[oc], b1 = bias[oc+1];
    float* o0 = &out[(((long)b*32 + oc)*132 + gy0 + row)*132 + gx0 + cs];
    float* o1 = o0 + 132*132;
#pragma unroll
    for (int j = 0; j < 11; j++) {
        float2 f = up2(acc2[j]);
        o0[j] = f.x + b0;
        o1[j] = f.y + b1;
    }
}

// ===========================================================================
// region layer fused. CHANGE: input row reads as 4x LDS.64; even pairs used
// directly as f32x2 operands, odd pairs built from register halves (3 pk2).
// Same FMA order -> bitwise-identical results.
// ===========================================================================
__global__ void __launch_bounds__(288)
region_kernel(const float* __restrict__ xin,
              const float* __restrict__ rg_g, const float* __restrict__ rg_b,
              const float* __restrict__ rg_m, const float* __restrict__ rg_v,
              const float* __restrict__ rg_w, const float* __restrict__ rg_cb,
              const float* __restrict__ bn2_g, const float* __restrict__ bn2_b,
              const float* __restrict__ bn2_m, const float* __restrict__ bn2_v,
              float* __restrict__ out) {
    __shared__ float smem[11152];   // s_in(6400)+s_w(4752); staging reuses [0,10368)
    __shared__ float s_scale[32], s_shift[32], s_cb[32], s_a2[32], s_b2[32];

    const int tile = blockIdx.x;
    const int b    = blockIdx.y;
    const int ti = tile >> 3, tj = tile & 7;
    const int th = (ti < 7) ? 18 : 6, tw = (tj < 7) ? 18 : 6;
    const int gy0 = ti * 18, gx0 = tj * 18;
    const int tid = threadIdx.x;

    if (tid < 32) {
        int p = tile*32 + tid;
        float a = rg_g[p] * rsqrtf(rg_v[p] + 1e-5f);
        s_scale[tid] = a;
        s_shift[tid] = rg_b[p] - rg_m[p]*a;
        s_cb[tid]    = rg_cb[p];
    } else if (tid < 64) {
        int c = tid - 32;
        float a2 = bn2_g[c] * rsqrtf(bn2_v[c] + 1e-5f);
        s_a2[c] = a2;
        s_b2[c] = bn2_b[c] - bn2_m[c]*a2;
    }

    const int hp = th + 2, wp = tw + 2;
    const int npx = tw / 6, npy = th / 6;
    const int pos = tid >> 5;
    const int oc  = tid & 31;
    const bool active = pos < npx * npy;
    const int prow = (pos / npx) * 6;
    const int pcol = (pos % npx) * 6;

    float* s_in = smem;
    float* s_w  = smem + 6400;   // layout: [(icl*9+k)*33 + oc]

    ull acc2[6][3];
#pragma unroll
    for (int i = 0; i < 6; i++)
#pragma unroll
        for (int j = 0; j < 3; j++) acc2[i][j] = 0ull;

    for (int chunk = 0; chunk < 2; chunk++) {
        const int ic0 = chunk * 16;
        __syncthreads();
        const int nin = 16 * hp * wp;
        for (int i = tid; i < nin; i += 288) {
            int icl = i / (hp*wp);
            int r = i % (hp*wp);
            int y = r / wp, xx = r % wp;
            float v = 0.f;
            if (y > 0 && y < hp-1 && xx > 0 && xx < wp-1) {
                float raw = xin[(((long)b*32 + ic0 + icl)*132 + gy0 + y - 1)*132 + gx0 + xx - 1];
                v = fmaxf(s_scale[ic0+icl]*raw + s_shift[ic0+icl], 0.f);
            }
            s_in[i] = v;
        }
        for (int i = tid; i < 32*144; i += 288) {
            int o  = i / 144;          // oc
            int kk = i % 144;          // icl*9 + k
            s_w[kk*33 + o] = rg_w[(long)tile*9216 + o*288 + ic0*9 + kk];
        }
        __syncthreads();

        if (active) {
            for (int icl = 0; icl < 16; icl++) {
                ull wr2[9];
#pragma unroll
                for (int k = 0; k < 9; k++) wr2[k] = bc2(s_w[(icl*9 + k)*33 + oc]);
                const float* ib = &s_in[icl*hp*wp + prow*wp + pcol];
#pragma unroll
                for (int r = 0; r < 8; r++) {
                    // all base offsets even -> 8B-aligned vector loads
                    const ull* ib2 = (const ull*)(ib + r*wp);
                    ull f0 = ib2[0], f1 = ib2[1], f2 = ib2[2], f3 = ib2[3];
                    ull p[7];
                    p[0] = f0; p[2] = f1; p[4] = f2; p[6] = f3;
                    float2 a0 = up2(f0), a1 = up2(f1), a2 = up2(f2), a3 = up2(f3);
                    p[1] = pk2(a0.y, a1.x);
                    p[3] = pk2(a1.y, a2.x);
                    p[5] = pk2(a2.y, a3.x);
#pragma unroll
                    for (int ky = 0; ky < 3; ky++) {
                        int orow = r - ky;
                        if (orow >= 0 && orow < 6) {
#pragma unroll
                            for (int kx = 0; kx < 3; kx++) {
                                ull w2 = wr2[ky*3 + kx];
                                ffma2(acc2[orow][0], p[kx    ], w2);
                                ffma2(acc2[orow][1], p[kx + 2], w2);
                                ffma2(acc2[orow][2], p[kx + 4], w2);
                            }
                        }
                    }
                }
            }
        }
    }

    __syncthreads();
    if (active) {
        const float cb = s_cb[oc];
#pragma unroll
        for (int i = 0; i < 6; i++)
#pragma unroll
            for (int jp = 0; jp < 3; jp++) {
                float2 f = up2(acc2[i][jp]);
                smem[(oc*th + prow + i)*tw + pcol + 2*jp    ] = f.x + cb;
                smem[(oc*th + prow + i)*tw + pcol + 2*jp + 1] = f.y + cb;
            }
    }
    __syncthreads();

    const int ph = th / 2, pw = tw / 2;
    const int npool = 32 * ph * pw;
    for (int i = tid; i < npool; i += 288) {
        int c = i / (ph*pw);
        int r = i % (ph*pw);
        int py = r / pw, px = r % pw;
        const float* cp = &smem[(c*th + 2*py)*tw + 2*px];
        const float* rp = &xin[(((long)b*32 + c)*132 + gy0 + 2*py)*132 + gx0 + 2*px];
        float v00 = fmaxf(cp[0]    + rp[0],     0.f);
        float v01 = fmaxf(cp[1]    + rp[1],     0.f);
        float v10 = fmaxf(cp[tw]   + rp[132],   0.f);
        float v11 = fmaxf(cp[tw+1] + rp[133],   0.f);
        float m = fmaxf(fmaxf(v00, v01), fmaxf(v10, v11));
        out[(((long)b*32 + c)*66 + ti*9 + py)*66 + tj*9 + px] = s_a2[c]*m + s_b2[c];
    }
}

// ===========================================================================
// conv2 / conv3: retry (256,3) with the slim ivb[12] body (small live set —
// expect <=80 regs without meaningful spills; occupancy 2->3 blocks/SM).
// ===========================================================================
template<int CIN, int HIN, int WIN, int HOUT, int WOUT>
__global__ void __launch_bounds__(256, 3)
conv8x8_relu_kernel(const float* __restrict__ in,
                    const float* __restrict__ w,
                    const float* __restrict__ bias,
                    float* __restrict__ out) {
    __shared__ float  s_in[8*15*40];
    __shared__ float2 s_w2[8*8*64];
    const int x0 = blockIdx.x * 32, y0 = blockIdx.y * 8;
    const int b = blockIdx.z;
    const int tid = threadIdx.x;
    const int pr  = tid >> 5;
    const int s   = tid & 31;
    const int row = s >> 2;
    const int cs  = (s & 3) * 8;

    ull acc2[8];
#pragma unroll
    for (int j = 0; j < 8; j++) acc2[j] = 0ull;

    for (int chunk = 0; chunk < CIN/8; chunk++) {
        const int ic0 = chunk * 8;
        __syncthreads();
        for (int i = tid; i < 8*15*40; i += 256) {
            int icl = i / 600;
            int r = (i / 40) % 15, c = i % 40;
            int iy = y0 + r, ix = x0 + c;
            float v = 0.f;
            if (c < 39 && iy < HIN && ix < WIN)
                v = in[(((long)b*CIN + ic0 + icl)*HIN + iy)*WIN + ix];
            s_in[i] = v;
        }
        for (int i = tid; i < 8*512; i += 256) {
            int p = i >> 9;
            int r = i & 511;
            float w0 = w[(2*p    )*CIN*64 + ic0*64 + r];
            float w1 = w[(2*p + 1)*CIN*64 + ic0*64 + r];
            s_w2[i] = make_float2(w0, w1);
        }
        __syncthreads();

        for (int icl = 0; icl < 8; icl++) {
#pragma unroll
            for (int ky = 0; ky < 8; ky++) {
                const float* ip = &s_in[icl*600 + (row + ky)*40 + cs];
                const float2* wrow = &s_w2[(pr*8 + icl)*64 + ky*8];
#pragma unroll
                for (int h = 0; h < 2; h++) {
                    float4 v0 = *(const float4*)(ip + h*4);
                    float4 v1 = *(const float4*)(ip + h*4 + 4);
                    float4 v2 = *(const float4*)(ip + h*4 + 8);
                    ull ivb[12];
                    ivb[0]=bc2(v0.x);  ivb[1]=bc2(v0.y);  ivb[2]=bc2(v0.z);  ivb[3]=bc2(v0.w);
                    ivb[4]=bc2(v1.x);  ivb[5]=bc2(v1.y);  ivb[6]=bc2(v1.z);  ivb[7]=bc2(v1.w);
                    ivb[8]=bc2(v2.x);  ivb[9]=bc2(v2.y);  ivb[10]=bc2(v2.z); ivb[11]=bc2(v2.w);
#pragma unroll
                    for (int kx = 0; kx < 4; kx++) {
                        ull w2 = *(const ull*)&wrow[h*4 + kx];
#pragma unroll
                        for (int j = 0; j < 8; j++)
                            ffma2(acc2[j], ivb[kx + j], w2);
                    }
                }
            }
        }
    }

    const int oy = y0 + row;
    if (oy < HOUT) {
        const int oc0 = 2*pr;
        const float b0 = bias[oc0], b1 = bias[oc0 + 1];
        float* o0 = &out[(((long)b*16 + oc0)*HOUT + oy)*WOUT];
        float* o1 = o0 + (long)HOUT*WOUT;
#pragma unroll
        for (int j = 0; j < 8; j++) {
            int ox = x0 + cs + j;
            if (ox < WOUT) {
                float2 f = up2(acc2[j]);
                o0[ox] = fmaxf(f.x + b0, 0.f);
                o1[ox] = fmaxf(f.y + b1, 0.f);
            }
        }
    }
}

// ===========================================================================
// conv4 (unchanged)
// ===========================================================================
__global__ void conv4_kernel(const float* __restrict__ in,
                             const float* __restrict__ w,
                             const float* __restrict__ bias,
                             float* __restrict__ out) {
    __shared__ float s_in[8*16*52];
    __shared__ float s_w[16*8*36];
    const int band = blockIdx.x;
    const int b = blockIdx.y;
    const int tid = threadIdx.x;
    const int ry0 = band * 6;

    float acc[9];
#pragma unroll
    for (int t = 0; t < 9; t++) acc[t] = 0.f;

    for (int chunk = 0; chunk < 2; chunk++) {
        const int ic0 = chunk * 8;
        __syncthreads();
        for (int i = tid; i < 8*16*52; i += 256) {
            int icl = i / (16*52);
            int r = (i / 52) % 16, c = i % 52;
            s_in[i] = in[(((long)b*16 + ic0 + icl)*52 + 12*band + r)*52 + c];
        }
        for (int i = tid; i < 16*8*36; i += 256) {
            int o = i / (8*36);
            int r = i % (8*36);
            int icl = r / 36, k = r % 36;
            s_w[i] = w[(o*16 + ic0 + icl)*36 + k];
        }
        __syncthreads();
#pragma unroll
        for (int t = 0; t < 9; t++) {
            int task = tid + t*256;
            if (task < 2304) {
                int oc = task / 144;
                int r = task % 144;
                int row = r / 24, cx = r % 24;
                float a = acc[t];
                for (int icl = 0; icl < 8; icl++) {
#pragma unroll
                    for (int ky = 0; ky < 6; ky++) {
                        const float* rp = &s_in[(icl*16 + 2*row + ky)*52 + 2*cx];
                        const float* wpp = &s_w[(oc*8 + icl)*36 + ky*6];
#pragma unroll
                        for (int kx = 0; kx < 6; kx++) a += rp[kx] * wpp[kx];
                    }
                }
                acc[t] = a;
            }
        }
    }
#pragma unroll
    for (int t = 0; t < 9; t++) {
        int task = tid + t*256;
        if (task < 2304) {
            int oc = task / 144;
            int r = task % 144;
            int row = r / 24, cx = r % 24;
            out[(((long)b*16 + oc)*24 + ry0 + row)*24 + cx] = fmaxf(acc[t] + bias[oc], 0.f);
        }
    }
}

// ===========================================================================
// conv5 (unchanged)
// ===========================================================================
__global__ void conv5_kernel(const float* __restrict__ in,
                             const float* __restrict__ w,
                             const float* __restrict__ bias,
                             float* __restrict__ out) {
    __shared__ float s_in[16*14*24];
    __shared__ float s_w[16*16*25];
    const int band = blockIdx.x;
    const int b = blockIdx.y;
    const int tid = threadIdx.x;
    const int ry0 = band * 10;

    for (int i = tid; i < 16*14*24; i += 256) {
        int icl = i / (14*24);
        int r = (i / 24) % 14, c = i % 24;
        s_in[i] = in[(((long)b*16 + icl)*24 + ry0 + r)*24 + c];
    }
    for (int i = tid; i < 16*16*25; i += 256)
        s_w[i] = w[i];
    __syncthreads();

#pragma unroll
    for (int t = 0; t < 13; t++) {
        int task = tid + t*256;
        if (task < 3200) {
            int oc = task / 200;
            int r = task % 200;
            int row = r / 20, cx = r % 20;
            float a = 0.f;
            for (int ic = 0; ic < 16; ic++) {
#pragma unroll
                for (int ky = 0; ky < 5; ky++) {
                    const float* rp = &s_in[(ic*14 + row + ky)*24 + cx];
                    const float* wpp = &s_w[(oc*16 + ic)*25 + ky*5];
#pragma unroll
                    for (int kx = 0; kx < 5; kx++) a += rp[kx] * wpp[kx];
                }
            }
            out[(((long)b*16 + oc)*20 + ry0 + row)*20 + cx] = fmaxf(a + bias[oc], 0.f);
        }
    }
}

// ===========================================================================
// split-K GEMM for fc1/fc2 (round-13, measured WIN)
// ===========================================================================
__global__ void __launch_bounds__(256)
gemm_splitk_kernel(const float* __restrict__ X,
                   const float* __restrict__ W,
                   float* __restrict__ part,
                   int N, int K, int Kc) {
    __shared__ float xs[64][68];
    __shared__ float ws[64][68];
    const int n0 = blockIdx.x * 64;
    const int ks = blockIdx.y * Kc;
    const int tid = threadIdx.x;
    const int tx = tid & 15, ty = tid >> 4;

    ull acc2[4][2];
#pragma unroll
    for (int i = 0; i < 4; i++)
#pragma unroll
        for (int j = 0; j < 2; j++) acc2[i][j] = 0ull;

    for (int k0 = ks; k0 < ks + Kc; k0 += 64) {
        __syncthreads();
        for (int i = tid; i < 64*64; i += 256) {
            int m = i >> 6, k = i & 63;
            xs[k][m] = X[m*K + k0 + k];
        }
        for (int i = tid; i < 64*64; i += 256) {
            int n = i >> 6, k = i & 63;
            ws[k][n] = W[(long)(n0 + n)*K + k0 + k];
        }
        __syncthreads();
#pragma unroll 8
        for (int k = 0; k < 64; k++) {
            float4 a4 = *(const float4*)&xs[k][ty*4];
            ull b0 = *(const ull*)&ws[k][tx*4];
            ull b1 = *(const ull*)&ws[k][tx*4 + 2];
            ull a0 = bc2(a4.x), a1 = bc2(a4.y), a2 = bc2(a4.z), a3 = bc2(a4.w);
            ffma2(acc2[0][0], a0, b0); ffma2(acc2[0][1], a0, b1);
            ffma2(acc2[1][0], a1, b0); ffma2(acc2[1][1], a1, b1);
            ffma2(acc2[2][0], a2, b0); ffma2(acc2[2][1], a2, b1);
            ffma2(acc2[3][0], a3, b0); ffma2(acc2[3][1], a3, b1);
        }
    }
    float* pb = part + (long)blockIdx.y * 64 * N;
#pragma unroll
    for (int i = 0; i < 4; i++) {
        int m = ty*4 + i;
#pragma unroll
        for (int j = 0; j < 2; j++) {
            int n = n0 + tx*4 + 2*j;
            float2 f = up2(acc2[i][j]);
            pb[m*N + n]     = f.x;
            pb[m*N + n + 1] = f.y;
        }
    }
}

// fuse: out = relu(sum_s part[s] + bias)
__global__ void fc_reduce_kernel(const float* __restrict__ part,
                                 const float* __restrict__ bias,
                                 float* __restrict__ out, int N) {
    int i = blockIdx.x * 256 + threadIdx.x;
    if (i >= 64 * N) return;
    int n = i % N;
    float s = part[i] + part[64*N + i] + part[2*64*N + i] + part[3*64*N + i];
    out[i] = fmaxf(s + bias[n], 0.f);
}

// ===========================================================================
// fc3 (unchanged)
// ===========================================================================
__global__ void fc3_kernel(const float* __restrict__ X,
                           const float* __restrict__ W,
                           const float* __restrict__ bias,
                           float* __restrict__ out) {
    const int warp = (blockIdx.x * 256 + threadIdx.x) >> 5;
    const int lane = threadIdx.x & 31;
    if (warp >= 768) return;
    const int m = warp / 12, n = warp % 12;
    float s = 0.f;
    for (int k = lane; k < 2048; k += 32)
        s += X[m*2048 + k] * W[n*2048 + k];
#pragma unroll
    for (int o = 16; o; o >>= 1) s += __shfl_xor_sync(0xFFFFFFFFu, s, o);
    if (lane == 0) out[m*12 + n] = s + bias[n];
}

// ===========================================================================
extern "C" void kernel_launch(void* const* d_in, const int* in_sizes, int n_in,
                              void* d_out, int out_size) {
    const float* x       = (const float*)d_in[0];
    const float* conv1_w = (const float*)d_in[1];
    const float* conv1_b = (const float*)d_in[2];
    const float* rg_g    = (const float*)d_in[3];
    const float* rg_b    = (const float*)d_in[4];
    const float* rg_m    = (const float*)d_in[5];
    const float* rg_v    = (const float*)d_in[6];
    const float* rg_w    = (const float*)d_in[7];
    const float* rg_cb   = (const float*)d_in[8];
    const float* bn2_g   = (const float*)d_in[9];
    const float* bn2_b   = (const float*)d_in[10];
    const float* bn2_m   = (const float*)d_in[11];
    const float* bn2_v   = (const float*)d_in[12];
    const float* conv2_w = (const float*)d_in[13];
    const float* conv2_b = (const float*)d_in[14];
    const float* conv3_w = (const float*)d_in[15];
    const float* conv3_b = (const float*)d_in[16];
    const float* conv4_w = (const float*)d_in[17];
    const float* conv4_b = (const float*)d_in[18];
    const float* conv5_w = (const float*)d_in[19];
    const float* conv5_b = (const float*)d_in[20];
    const float* fc1_w   = (const float*)d_in[21];
    const float* fc1_b   = (const float*)d_in[22];
    const float* fc2_w   = (const float*)d_in[23];
    const float* fc2_b   = (const float*)d_in[24];
    const float* fc3_w   = (const float*)d_in[25];
    const float* fc3_b   = (const float*)d_in[26];

    float *b1, *b2, *b3, *b4, *b5, *b6, *f1, *f2, *pp, *dm;
    cudaGetSymbolAddress((void**)&b1, g_buf1);
    cudaGetSymbolAddress((void**)&b2, g_buf2);
    cudaGetSymbolAddress((void**)&b3, g_buf3);
    cudaGetSymbolAddress((void**)&b4, g_buf4);
    cudaGetSymbolAddress((void**)&b5, g_buf5);
    cudaGetSymbolAddress((void**)&b6, g_buf6);
    cudaGetSymbolAddress((void**)&f1, g_fc1o);
    cudaGetSymbolAddress((void**)&f2, g_fc2o);
    cudaGetSymbolAddress((void**)&pp, g_part);
    cudaGetSymbolAddress((void**)&dm, g_dummy);

    // one tiny launch: ncu fixed-index capture (4th launch) lands on conv2
    nudge_kernel<<<1, 32>>>(dm);

    conv1_kernel<<<dim3(12, 8, 64), 264>>>(x, conv1_w, conv1_b, b1);
    region_kernel<<<dim3(64, 64), 288>>>(b1, rg_g, rg_b, rg_m, rg_v, rg_w, rg_cb,
                                         bn2_g, bn2_b, bn2_m, bn2_v, b2);
    conv8x8_relu_kernel<32, 66, 66, 59, 59><<<dim3(2, 8, 64), 256>>>(b2, conv2_w, conv2_b, b3);
    conv8x8_relu_kernel<16, 59, 59, 52, 52><<<dim3(2, 7, 64), 256>>>(b3, conv3_w, conv3_b, b4);
    conv4_kernel<<<dim3(4, 64), 256>>>(b4, conv4_w, conv4_b, b5);
    conv5_kernel<<<dim3(2, 64), 256>>>(b5, conv5_w, conv5_b, b6);
    // fc1: split-K S=4 (Kc=1600), then fuse
    gemm_splitk_kernel<<<dim3(64, 4), 256>>>(b6, fc1_w, pp, 4096, 6400, 1600);
    fc_reduce_kernel<<<(64*4096 + 255)/256, 256>>>(pp, fc1_b, f1, 4096);
    // fc2: split-K S=4 (Kc=1024), then fuse
    gemm_splitk_kernel<<<dim3(32, 4), 256>>>(f1, fc2_w, pp, 2048, 4096, 1024);
    fc_reduce_kernel<<<(64*2048 + 255)/256, 256>>>(pp, fc2_b, f2, 2048);
    fc3_kernel<<<96, 256>>>(f2, fc3_w, fc3_b, (float*)d_out);
}

// round 17
// speedup vs baseline: 1.3606x; 1.0108x over previous
#include <cuda_runtime.h>
#include <cuda_bf16.h>
#include <cstdint>

typedef unsigned long long ull;

// ---- packed f32x2 helpers -------------------------------------------------
__device__ __forceinline__ ull pk2(float lo, float hi) {
    ull r; asm("mov.b64 %0, {%1, %2};" : "=l"(r) : "f"(lo), "f"(hi)); return r;
}
__device__ __forceinline__ ull bc2(float v) { return pk2(v, v); }
__device__ __forceinline__ void ffma2(ull& d, ull a, ull b) {
    asm("fma.rn.f32x2 %0, %1, %2, %3;" : "=l"(d) : "l"(a), "l"(b), "l"(d));
}
__device__ __forceinline__ float2 up2(ull v) {
    float2 f; asm("mov.b64 {%0, %1}, %2;" : "=f"(f.x), "=f"(f.y) : "l"(v)); return f;
}

// ---------------- scratch buffers ------------------------------------------
__device__ float g_buf1[64u*32u*132u*132u]; // conv1 out
__device__ float g_buf2[64u*32u*66u*66u];   // region+pool+bn2 out
__device__ float g_buf3[64u*16u*59u*59u];   // conv2 out
__device__ float g_buf4[64u*16u*52u*52u];   // conv3 out
__device__ float g_buf5[64u*16u*24u*24u];   // conv4 out
__device__ float g_buf6[64u*16u*20u*20u];   // conv5 out (fc input)
__device__ float g_fc1o[64u*4096u];
__device__ float g_fc2o[64u*2048u];
__device__ float g_part[10u*64u*4096u];     // split-K partials (10 splits max)
__device__ float g_dummy[32];

// dummy launches: land the ncu fixed-index capture window on region<18,18>
__global__ void nudge_kernel(float* p) { p[threadIdx.x] = 0.f; }

// ===========================================================================
// conv1 (round-4 f32x2) — ~96% of the FFMA2-pipe limit, do not touch.
// ===========================================================================
__global__ void __launch_bounds__(264, 2)
conv1_kernel(const float* __restrict__ x,
             const float* __restrict__ w,
             const float* __restrict__ bias,
             float* __restrict__ out) {
    __shared__ float  s_in[3*32*76];
    __shared__ float2 s_w2[2*363];
    const int t   = blockIdx.x;
    const int ti  = t >> 1, tj = t & 1;
    const int gy0 = ti * 22, gx0 = tj * 66;
    const int ocg = blockIdx.y;
    const int b   = blockIdx.z;
    const int tid = threadIdx.x;

    for (int i = tid; i < 2*363; i += 264) {
        int h = i / 363, idx = i % 363;
        int oc = ocg*4 + h*2;
        s_w2[i] = make_float2(w[oc*363 + idx], w[(oc+1)*363 + idx]);
    }
    for (int i = tid; i < 3*32*76; i += 264) {
        int c  = i / 2432;
        int r  = (i / 76) % 32, cc = i % 76;
        s_in[i] = x[((b*3 + c)*142 + gy0 + r)*142 + gx0 + cc];
    }
    __syncthreads();

    const int half = tid / 132;
    const int s    = tid % 132;
    const int row  = s / 6;
    const int cs   = (s % 6) * 11;

    ull acc2[11];
#pragma unroll
    for (int j = 0; j < 11; j++) acc2[j] = 0ull;

    for (int c = 0; c < 3; c++) {
        for (int ky = 0; ky < 11; ky++) {
            const float* ip = &s_in[c*2432 + (row + ky)*76 + cs];
            ull ivb[21];
#pragma unroll
            for (int j = 0; j < 21; j++) ivb[j] = bc2(ip[j]);
            const float2* wrow = &s_w2[half*363 + c*121 + ky*11];
#pragma unroll
            for (int kx = 0; kx < 11; kx++) {
                ull w2 = *(const ull*)&wrow[kx];
#pragma unroll
                for (int j = 0; j < 11; j++)
                    ffma2(acc2[j], ivb[kx + j], w2);
            }
        }
    }
    const int oc = ocg*4 + half*2;
    const float b0 = bias[oc], b1 = bias[oc+1];
    float* o0 = &out[(((long)b*32 + oc)*132 + gy0 + row)*132 + gx0 + cs];
    float* o1 = o0 + 132*132;
#pragma unroll
    for (int j = 0; j < 11; j++) {
        float2 f = up2(acc2[j]);
        o0[j] = f.x + b0;
        o1[j] = f.y + b1;
    }
}

// ===========================================================================
// region layer, template-specialized on tile size (TH,TW) and placement MODE.
// MODE: 0 interior, 1 right col (tj=7), 2 bottom row (ti=7), 3 corner.
// ===========================================================================
template<int TH, int TW, int MODE>
__global__ void __launch_bounds__(288)
region_tile_kernel(const float* __restrict__ xin,
                   const float* __restrict__ rg_g, const float* __restrict__ rg_b,
                   const float* __restrict__ rg_m, const float* __restrict__ rg_v,
                   const float* __restrict__ rg_w, const float* __restrict__ rg_cb,
                   const float* __restrict__ bn2_g, const float* __restrict__ bn2_b,
                   const float* __restrict__ bn2_m, const float* __restrict__ bn2_v,
                   float* __restrict__ out) {
    __shared__ float smem[11152];
    __shared__ float s_scale[32], s_shift[32], s_cb[32], s_a2[32], s_b2[32];

    int ti, tj;
    if      (MODE == 0) { ti = blockIdx.x / 7; tj = blockIdx.x % 7; }
    else if (MODE == 1) { ti = blockIdx.x;     tj = 7; }
    else if (MODE == 2) { ti = 7;              tj = blockIdx.x; }
    else                { ti = 7;              tj = 7; }
    const int tile = ti*8 + tj;
    const int b    = blockIdx.y;
    const int gy0 = ti * 18, gx0 = tj * 18;
    const int tid = threadIdx.x;

    if (tid < 32) {
        int p = tile*32 + tid;
        float a = rg_g[p] * rsqrtf(rg_v[p] + 1e-5f);
        s_scale[tid] = a;
        s_shift[tid] = rg_b[p] - rg_m[p]*a;
        s_cb[tid]    = rg_cb[p];
    } else if (tid < 64) {
        int c = tid - 32;
        float a2 = bn2_g[c] * rsqrtf(bn2_v[c] + 1e-5f);
        s_a2[c] = a2;
        s_b2[c] = bn2_b[c] - bn2_m[c]*a2;
    }

    constexpr int hp = TH + 2, wp = TW + 2;
    constexpr int npx = TW / 6, npy = TH / 6;
    const int pos = tid >> 5;
    const int oc  = tid & 31;
    const bool active = pos < npx * npy;
    const int prow = (pos / npx) * 6;
    const int pcol = (pos % npx) * 6;

    float* s_in = smem;
    float* s_w  = smem + 6400;   // layout: [(icl*9+k)*33 + oc]

    ull acc2[6][3];
#pragma unroll
    for (int i = 0; i < 6; i++)
#pragma unroll
        for (int j = 0; j < 3; j++) acc2[i][j] = 0ull;

    for (int chunk = 0; chunk < 2; chunk++) {
        const int ic0 = chunk * 16;
        __syncthreads();
        constexpr int nin = 16 * hp * wp;
        for (int i = tid; i < nin; i += 288) {
            int icl = i / (hp*wp);
            int r = i % (hp*wp);
            int y = r / wp, xx = r % wp;
            float v = 0.f;
            if (y > 0 && y < hp-1 && xx > 0 && xx < wp-1) {
                float raw = xin[(((long)b*32 + ic0 + icl)*132 + gy0 + y - 1)*132 + gx0 + xx - 1];
                v = fmaxf(s_scale[ic0+icl]*raw + s_shift[ic0+icl], 0.f);
            }
            s_in[i] = v;
        }
        for (int i = tid; i < 32*144; i += 288) {
            int o  = i / 144;
            int kk = i % 144;
            s_w[kk*33 + o] = rg_w[(long)tile*9216 + o*288 + ic0*9 + kk];
        }
        __syncthreads();

        if (active) {
            for (int icl = 0; icl < 16; icl++) {
                ull wr2[9];
#pragma unroll
                for (int k = 0; k < 9; k++) wr2[k] = bc2(s_w[(icl*9 + k)*33 + oc]);
                const float* ib = &s_in[icl*hp*wp + prow*wp + pcol];
#pragma unroll
                for (int r = 0; r < 8; r++) {
                    const ull* ib2 = (const ull*)(ib + r*wp);
                    ull f0 = ib2[0], f1 = ib2[1], f2 = ib2[2], f3 = ib2[3];
                    ull p[7];
                    p[0] = f0; p[2] = f1; p[4] = f2; p[6] = f3;
                    float2 a0 = up2(f0), a1 = up2(f1), a2 = up2(f2), a3 = up2(f3);
                    p[1] = pk2(a0.y, a1.x);
                    p[3] = pk2(a1.y, a2.x);
                    p[5] = pk2(a2.y, a3.x);
#pragma unroll
                    for (int ky = 0; ky < 3; ky++) {
                        int orow = r - ky;
                        if (orow >= 0 && orow < 6) {
#pragma unroll
                            for (int kx = 0; kx < 3; kx++) {
                                ull w2 = wr2[ky*3 + kx];
                                ffma2(acc2[orow][0], p[kx    ], w2);
                                ffma2(acc2[orow][1], p[kx + 2], w2);
                                ffma2(acc2[orow][2], p[kx + 4], w2);
                            }
                        }
                    }
                }
            }
        }
    }

    __syncthreads();
    if (active) {
        const float cb = s_cb[oc];
#pragma unroll
        for (int i = 0; i < 6; i++)
#pragma unroll
            for (int jp = 0; jp < 3; jp++) {
                float2 f = up2(acc2[i][jp]);
                smem[(oc*TH + prow + i)*TW + pcol + 2*jp    ] = f.x + cb;
                smem[(oc*TH + prow + i)*TW + pcol + 2*jp + 1] = f.y + cb;
            }
    }
    __syncthreads();

    constexpr int ph = TH / 2, pw = TW / 2;
    constexpr int npool = 32 * ph * pw;
    for (int i = tid; i < npool; i += 288) {
        int c = i / (ph*pw);
        int r = i % (ph*pw);
        int py = r / pw, px = r % pw;
        const float* cp = &smem[(c*TH + 2*py)*TW + 2*px];
        const float* rp = &xin[(((long)b*32 + c)*132 + gy0 + 2*py)*132 + gx0 + 2*px];
        float v00 = fmaxf(cp[0]    + rp[0],     0.f);
        float v01 = fmaxf(cp[1]    + rp[1],     0.f);
        float v10 = fmaxf(cp[TW]   + rp[132],   0.f);
        float v11 = fmaxf(cp[TW+1] + rp[133],   0.f);
        float m = fmaxf(fmaxf(v00, v01), fmaxf(v10, v11));
        out[(((long)b*32 + c)*66 + ti*9 + py)*66 + tj*9 + px] = s_a2[c]*m + s_b2[c];
    }
}

// ===========================================================================
// conv2 / conv3: (256,3), slim ivb[12] body — measured WIN; unchanged.
// ===========================================================================
template<int CIN, int HIN, int WIN, int HOUT, int WOUT>
__global__ void __launch_bounds__(256, 3)
conv8x8_relu_kernel(const float* __restrict__ in,
                    const float* __restrict__ w,
                    const float* __restrict__ bias,
                    float* __restrict__ out) {
    __shared__ float  s_in[8*15*40];
    __shared__ float2 s_w2[8*8*64];
    const int x0 = blockIdx.x * 32, y0 = blockIdx.y * 8;
    const int b = blockIdx.z;
    const int tid = threadIdx.x;
    const int pr  = tid >> 5;
    const int s   = tid & 31;
    const int row = s >> 2;
    const int cs  = (s & 3) * 8;

    ull acc2[8];
#pragma unroll
    for (int j = 0; j < 8; j++) acc2[j] = 0ull;

    for (int chunk = 0; chunk < CIN/8; chunk++) {
        const int ic0 = chunk * 8;
        __syncthreads();
        for (int i = tid; i < 8*15*40; i += 256) {
            int icl = i / 600;
            int r = (i / 40) % 15, c = i % 40;
            int iy = y0 + r, ix = x0 + c;
            float v = 0.f;
            if (c < 39 && iy < HIN && ix < WIN)
                v = in[(((long)b*CIN + ic0 + icl)*HIN + iy)*WIN + ix];
            s_in[i] = v;
        }
        for (int i = tid; i < 8*512; i += 256) {
            int p = i >> 9;
            int r = i & 511;
            float w0 = w[(2*p    )*CIN*64 + ic0*64 + r];
            float w1 = w[(2*p + 1)*CIN*64 + ic0*64 + r];
            s_w2[i] = make_float2(w0, w1);
        }
        __syncthreads();

        for (int icl = 0; icl < 8; icl++) {
#pragma unroll
            for (int ky = 0; ky < 8; ky++) {
                const float* ip = &s_in[icl*600 + (row + ky)*40 + cs];
                const float2* wrow = &s_w2[(pr*8 + icl)*64 + ky*8];
#pragma unroll
                for (int h = 0; h < 2; h++) {
                    float4 v0 = *(const float4*)(ip + h*4);
                    float4 v1 = *(const float4*)(ip + h*4 + 4);
                    float4 v2 = *(const float4*)(ip + h*4 + 8);
                    ull ivb[12];
                    ivb[0]=bc2(v0.x);  ivb[1]=bc2(v0.y);  ivb[2]=bc2(v0.z);  ivb[3]=bc2(v0.w);
                    ivb[4]=bc2(v1.x);  ivb[5]=bc2(v1.y);  ivb[6]=bc2(v1.z);  ivb[7]=bc2(v1.w);
                    ivb[8]=bc2(v2.x);  ivb[9]=bc2(v2.y);  ivb[10]=bc2(v2.z); ivb[11]=bc2(v2.w);
#pragma unroll
                    for (int kx = 0; kx < 4; kx++) {
                        ull w2 = *(const ull*)&wrow[h*4 + kx];
#pragma unroll
                        for (int j = 0; j < 8; j++)
                            ffma2(acc2[j], ivb[kx + j], w2);
                    }
                }
            }
        }
    }

    const int oy = y0 + row;
    if (oy < HOUT) {
        const int oc0 = 2*pr;
        const float b0 = bias[oc0], b1 = bias[oc0 + 1];
        float* o0 = &out[(((long)b*16 + oc0)*HOUT + oy)*WOUT];
        float* o1 = o0 + (long)HOUT*WOUT;
#pragma unroll
        for (int j = 0; j < 8; j++) {
            int ox = x0 + cs + j;
            if (ox < WOUT) {
                float2 f = up2(acc2[j]);
                o0[ox] = fmaxf(f.x + b0, 0.f);
                o1[ox] = fmaxf(f.y + b1, 0.f);
            }
        }
    }
}

// ===========================================================================
// conv4 (unchanged)
// ===========================================================================
__global__ void conv4_kernel(const float* __restrict__ in,
                             const float* __restrict__ w,
                             const float* __restrict__ bias,
                             float* __restrict__ out) {
    __shared__ float s_in[8*16*52];
    __shared__ float s_w[16*8*36];
    const int band = blockIdx.x;
    const int b = blockIdx.y;
    const int tid = threadIdx.x;
    const int ry0 = band * 6;

    float acc[9];
#pragma unroll
    for (int t = 0; t < 9; t++) acc[t] = 0.f;

    for (int chunk = 0; chunk < 2; chunk++) {
        const int ic0 = chunk * 8;
        __syncthreads();
        for (int i = tid; i < 8*16*52; i += 256) {
            int icl = i / (16*52);
            int r = (i / 52) % 16, c = i % 52;
            s_in[i] = in[(((long)b*16 + ic0 + icl)*52 + 12*band + r)*52 + c];
        }
        for (int i = tid; i < 16*8*36; i += 256) {
            int o = i / (8*36);
            int r = i % (8*36);
            int icl = r / 36, k = r % 36;
            s_w[i] = w[(o*16 + ic0 + icl)*36 + k];
        }
        __syncthreads();
#pragma unroll
        for (int t = 0; t < 9; t++) {
            int task = tid + t*256;
            if (task < 2304) {
                int oc = task / 144;
                int r = task % 144;
                int row = r / 24, cx = r % 24;
                float a = acc[t];
                for (int icl = 0; icl < 8; icl++) {
#pragma unroll
                    for (int ky = 0; ky < 6; ky++) {
                        const float* rp = &s_in[(icl*16 + 2*row + ky)*52 + 2*cx];
                        const float* wpp = &s_w[(oc*8 + icl)*36 + ky*6];
#pragma unroll
                        for (int kx = 0; kx < 6; kx++) a += rp[kx] * wpp[kx];
                    }
                }
                acc[t] = a;
            }
        }
    }
#pragma unroll
    for (int t = 0; t < 9; t++) {
        int task = tid + t*256;
        if (task < 2304) {
            int oc = task / 144;
            int r = task % 144;
            int row = r / 24, cx = r % 24;
            out[(((long)b*16 + oc)*24 + ry0 + row)*24 + cx] = fmaxf(acc[t] + bias[oc], 0.f);
        }
    }
}

// ===========================================================================
// conv5 (unchanged)
// ===========================================================================
__global__ void conv5_kernel(const float* __restrict__ in,
                             const float* __restrict__ w,
                             const float* __restrict__ bias,
                             float* __restrict__ out) {
    __shared__ float s_in[16*14*24];
    __shared__ float s_w[16*16*25];
    const int band = blockIdx.x;
    const int b = blockIdx.y;
    const int tid = threadIdx.x;
    const int ry0 = band * 10;

    for (int i = tid; i < 16*14*24; i += 256) {
        int icl = i / (14*24);
        int r = (i / 24) % 14, c = i % 24;
        s_in[i] = in[(((long)b*16 + icl)*24 + ry0 + r)*24 + c];
    }
    for (int i = tid; i < 16*16*25; i += 256)
        s_w[i] = w[i];
    __syncthreads();

#pragma unroll
    for (int t = 0; t < 13; t++) {
        int task = tid + t*256;
        if (task < 3200) {
            int oc = task / 200;
            int r = task % 200;
            int row = r / 20, cx = r % 20;
            float a = 0.f;
            for (int ic = 0; ic < 16; ic++) {
#pragma unroll
                for (int ky = 0; ky < 5; ky++) {
                    const float* rp = &s_in[(ic*14 + row + ky)*24 + cx];
                    const float* wpp = &s_w[(oc*16 + ic)*25 + ky*5];
#pragma unroll
                    for (int kx = 0; kx < 5; kx++) a += rp[kx] * wpp[kx];
                }
            }
            out[(((long)b*16 + oc)*20 + ry0 + row)*20 + cx] = fmaxf(a + bias[oc], 0.f);
        }
    }
}

// ===========================================================================
// split-K GEMM for fc1/fc2. Kc MUST be a multiple of 64 (panel width).
// ===========================================================================
__global__ void __launch_bounds__(256)
gemm_splitk_kernel(const float* __restrict__ X,
                   const float* __restrict__ W,
                   float* __restrict__ part,
                   int N, int K, int Kc) {
    __shared__ float xs[64][68];
    __shared__ float ws[64][68];
    const int n0 = blockIdx.x * 64;
    const int ks = blockIdx.y * Kc;
    const int tid = threadIdx.x;
    const int tx = tid & 15, ty = tid >> 4;

    ull acc2[4][2];
#pragma unroll
    for (int i = 0; i < 4; i++)
#pragma unroll
        for (int j = 0; j < 2; j++) acc2[i][j] = 0ull;

    for (int k0 = ks; k0 < ks + Kc; k0 += 64) {
        __syncthreads();
        for (int i = tid; i < 64*64; i += 256) {
            int m = i >> 6, k = i & 63;
            xs[k][m] = X[m*K + k0 + k];
        }
        for (int i = tid; i < 64*64; i += 256) {
            int n = i >> 6, k = i & 63;
            ws[k][n] = W[(long)(n0 + n)*K + k0 + k];
        }
        __syncthreads();
#pragma unroll 8
        for (int k = 0; k < 64; k++) {
            float4 a4 = *(const float4*)&xs[k][ty*4];
            ull b0 = *(const ull*)&ws[k][tx*4];
            ull b1 = *(const ull*)&ws[k][tx*4 + 2];
            ull a0 = bc2(a4.x), a1 = bc2(a4.y), a2 = bc2(a4.z), a3 = bc2(a4.w);
            ffma2(acc2[0][0], a0, b0); ffma2(acc2[0][1], a0, b1);
            ffma2(acc2[1][0], a1, b0); ffma2(acc2[1][1], a1, b1);
            ffma2(acc2[2][0], a2, b0); ffma2(acc2[2][1], a2, b1);
            ffma2(acc2[3][0], a3, b0); ffma2(acc2[3][1], a3, b1);
        }
    }
    float* pb = part + (long)blockIdx.y * 64 * N;
#pragma unroll
    for (int i = 0; i < 4; i++) {
        int m = ty*4 + i;
#pragma unroll
        for (int j = 0; j < 2; j++) {
            int n = n0 + tx*4 + 2*j;
            float2 f = up2(acc2[i][j]);
            pb[m*N + n]     = f.x;
            pb[m*N + n + 1] = f.y;
        }
    }
}

// fuse: out = relu(sum_{s<S} part[s] + bias)
template<int S>
__global__ void fc_reduce_kernel(const float* __restrict__ part,
                                 const float* __restrict__ bias,
                                 float* __restrict__ out, int N) {
    int i = blockIdx.x * 256 + threadIdx.x;
    if (i >= 64 * N) return;
    int n = i % N;
    float s = 0.f;
#pragma unroll
    for (int p = 0; p < S; p++) s += part[(long)p*64*N + i];
    out[i] = fmaxf(s + bias[n], 0.f);
}

// ===========================================================================
// fc3 (unchanged)
// ===========================================================================
__global__ void fc3_kernel(const float* __restrict__ X,
                           const float* __restrict__ W,
                           const float* __restrict__ bias,
                           float* __restrict__ out) {
    const int warp = (blockIdx.x * 256 + threadIdx.x) >> 5;
    const int lane = threadIdx.x & 31;
    if (warp >= 768) return;
    const int m = warp / 12, n = warp % 12;
    float s = 0.f;
    for (int k = lane; k < 2048; k += 32)
        s += X[m*2048 + k] * W[n*2048 + k];
#pragma unroll
    for (int o = 16; o; o >>= 1) s += __shfl_xor_sync(0xFFFFFFFFu, s, o);
    if (lane == 0) out[m*12 + n] = s + bias[n];
}

// ===========================================================================
extern "C" void kernel_launch(void* const* d_in, const int* in_sizes, int n_in,
                              void* d_out, int out_size) {
    const float* x       = (const float*)d_in[0];
    const float* conv1_w = (const float*)d_in[1];
    const float* conv1_b = (const float*)d_in[2];
    const float* rg_g    = (const float*)d_in[3];
    const float* rg_b    = (const float*)d_in[4];
    const float* rg_m    = (const float*)d_in[5];
    const float* rg_v    = (const float*)d_in[6];
    const float* rg_w    = (const float*)d_in[7];
    const float* rg_cb   = (const float*)d_in[8];
    const float* bn2_g   = (const float*)d_in[9];
    const float* bn2_b   = (const float*)d_in[10];
    const float* bn2_m   = (const float*)d_in[11];
    const float* bn2_v   = (const float*)d_in[12];
    const float* conv2_w = (const float*)d_in[13];
    const float* conv2_b = (const float*)d_in[14];
    const float* conv3_w = (const float*)d_in[15];
    const float* conv3_b = (const float*)d_in[16];
    const float* conv4_w = (const float*)d_in[17];
    const float* conv4_b = (const float*)d_in[18];
    const float* conv5_w = (const float*)d_in[19];
    const float* conv5_b = (const float*)d_in[20];
    const float* fc1_w   = (const float*)d_in[21];
    const float* fc1_b   = (const float*)d_in[22];
    const float* fc2_w   = (const float*)d_in[23];
    const float* fc2_b   = (const float*)d_in[24];
    const float* fc3_w   = (const float*)d_in[25];
    const float* fc3_b   = (const float*)d_in[26];

    float *b1, *b2, *b3, *b4, *b5, *b6, *f1, *f2, *pp, *dm;
    cudaGetSymbolAddress((void**)&b1, g_buf1);
    cudaGetSymbolAddress((void**)&b2, g_buf2);
    cudaGetSymbolAddress((void**)&b3, g_buf3);
    cudaGetSymbolAddress((void**)&b4, g_buf4);
    cudaGetSymbolAddress((void**)&b5, g_buf5);
    cudaGetSymbolAddress((void**)&b6, g_buf6);
    cudaGetSymbolAddress((void**)&f1, g_fc1o);
    cudaGetSymbolAddress((void**)&f2, g_fc2o);
    cudaGetSymbolAddress((void**)&pp, g_part);
    cudaGetSymbolAddress((void**)&dm, g_dummy);

    // two tiny launches: ncu capture (4th launch) lands on region<18,18>
    nudge_kernel<<<1, 32>>>(dm);
    nudge_kernel<<<1, 32>>>(dm);

    conv1_kernel<<<dim3(12, 8, 64), 264>>>(x, conv1_w, conv1_b, b1);
    // region: 4 specialized variants
    region_tile_kernel<18,18,0><<<dim3(49, 64), 288>>>(b1, rg_g, rg_b, rg_m, rg_v, rg_w, rg_cb,
                                                       bn2_g, bn2_b, bn2_m, bn2_v, b2);
    region_tile_kernel<18, 6,1><<<dim3(7, 64), 288>>>(b1, rg_g, rg_b, rg_m, rg_v, rg_w, rg_cb,
                                                      bn2_g, bn2_b, bn2_m, bn2_v, b2);
    region_tile_kernel< 6,18,2><<<dim3(7, 64), 288>>>(b1, rg_g, rg_b, rg_m, rg_v, rg_w, rg_cb,
                                                      bn2_g, bn2_b, bn2_m, bn2_v, b2);
    region_tile_kernel< 6, 6,3><<<dim3(1, 64), 288>>>(b1, rg_g, rg_b, rg_m, rg_v, rg_w, rg_cb,
                                                      bn2_g, bn2_b, bn2_m, bn2_v, b2);
    conv8x8_relu_kernel<32, 66, 66, 59, 59><<<dim3(2, 8, 64), 256>>>(b2, conv2_w, conv2_b, b3);
    conv8x8_relu_kernel<16, 59, 59, 52, 52><<<dim3(2, 7, 64), 256>>>(b3, conv3_w, conv3_b, b4);
    conv4_kernel<<<dim3(4, 64), 256>>>(b4, conv4_w, conv4_b, b5);
    conv5_kernel<<<dim3(2, 64), 256>>>(b5, conv5_w, conv5_b, b6);
    // fc1: split-K S=10 (Kc=640 = 10 panels of 64), then fuse
    gemm_splitk_kernel<<<dim3(64, 10), 256>>>(b6, fc1_w, pp, 4096, 6400, 640);
    fc_reduce_kernel<10><<<(64*4096 + 255)/256, 256>>>(pp, fc1_b, f1, 4096);
    // fc2: split-K S=8 (Kc=512 = 8 panels of 64), then fuse
    gemm_splitk_kernel<<<dim3(32, 8), 256>>>(f1, fc2_w, pp, 2048, 4096, 512);
    fc_reduce_kernel<8><<<(64*2048 + 255)/256, 256>>>(pp, fc2_b, f2, 2048);
    fc3_kernel<<<96, 256>>>(f2, fc3_w, fc3_b, (float*)d_out);
}